// round 13
// baseline (speedup 1.0000x reference)
#include <cuda_runtime.h>
#include <cuda_fp16.h>
#include <cstdint>

// ---------------------------------------------------------------------------
// MultiAxisAttention (Swin window attention) — fp16 HMMA GEMMs, m16n8k16,
// fp32 accumulate. R13: GEMM 256 thr / 8 warps, warp tile 64x32 (acc 64 regs
// -> 2 CTAs x 16 warps/SM), 4-stage cp.async ring. Attention = R8-proven.
// ---------------------------------------------------------------------------

#define M_REAL 153664            // 16*196*49
#define M_PAD  153728            // 1201*128
#define NWIN   3136
#define HEADS  16
#define WIN    49
#define KDIM   512

__device__ __half g_qkvh[236027904];   // M_REAL*1536
__device__ __half g_atth[78708736];    // M_PAD*512 (pad rows zeroed)
__device__ __half g_xh  [78708736];    // M_PAD*512 (pad rows zeroed)
__device__ __half g_wqkvT[786432];     // [1536][512]
__device__ __half g_woutT[262144];     // [512][512]

// ------------------------------ helpers -----------------------------------
__device__ __forceinline__ float tf32r(float f) {
    unsigned u;
    asm("cvt.rna.tf32.f32 %0, %1;" : "=r"(u) : "f"(f));
    return __uint_as_float(u);
}
__device__ __forceinline__ uint32_t smem_u32(const void* p) {
    uint32_t a;
    asm("{ .reg .u64 t; cvta.to.shared.u64 t, %1; cvt.u32.u64 %0, t; }"
        : "=r"(a) : "l"(p));
    return a;
}
__device__ __forceinline__ void cp16(uint32_t dst, const void* src) {
    asm volatile("cp.async.cg.shared.global [%0], [%1], 16;\n"
                 :: "r"(dst), "l"(src));
}
#define CP_COMMIT() asm volatile("cp.async.commit_group;\n" ::: "memory")
#define CP_WAIT(n)  asm volatile("cp.async.wait_group %0;\n" :: "n"(n) : "memory")

__device__ __forceinline__ void ldsm4(unsigned* r, uint32_t a) {
    asm volatile("ldmatrix.sync.aligned.m8n8.x4.shared.b16 {%0,%1,%2,%3}, [%4];"
                 : "=r"(r[0]), "=r"(r[1]), "=r"(r[2]), "=r"(r[3]) : "r"(a));
}
__device__ __forceinline__ void mma_f16(float* d, const unsigned* a, const unsigned* b) {
    asm volatile(
        "mma.sync.aligned.m16n8k16.row.col.f32.f16.f16.f32 "
        "{%0,%1,%2,%3}, {%4,%5,%6,%7}, {%8,%9}, {%0,%1,%2,%3};\n"
        : "+f"(d[0]), "+f"(d[1]), "+f"(d[2]), "+f"(d[3])
        : "r"(a[0]), "r"(a[1]), "r"(a[2]), "r"(a[3]),
          "r"(b[0]), "r"(b[1]));
}
__device__ __forceinline__ void mma_tf32(float* d, const unsigned* a, const unsigned* b) {
    asm volatile(
        "mma.sync.aligned.m16n8k8.row.col.f32.tf32.tf32.f32 "
        "{%0,%1,%2,%3}, {%4,%5,%6,%7}, {%8,%9}, {%0,%1,%2,%3};\n"
        : "+f"(d[0]), "+f"(d[1]), "+f"(d[2]), "+f"(d[3])
        : "r"(a[0]), "r"(a[1]), "r"(a[2]), "r"(a[3]),
          "r"(b[0]), "r"(b[1]));
}

__device__ __forceinline__ void storeC(float* C, size_t idx, float a, float b) {
    *(float2*)(C + idx) = make_float2(a, b);
}
__device__ __forceinline__ void storeC(__half* C, size_t idx, float a, float b) {
    *(__half2*)(C + idx) = __floats2half2_rn(a, b);
}

// ----------------------------- GEMM (fp16) ---------------------------------
// CTA 128x128, BK=32, 256 threads = 8 warps (2x4), warp tile 64x32.
// 4-stage cp.async ring, wait_group(2), ONE __syncthreads per stage.
// A [M][512] half row-major; B = WT [N][512] half row-major.
#define BM 128
#define BN 128
#define BK 32
#define RSH 40
#define OP_HALVES (128 * RSH)          // 5120 per operand per stage
#define STG_HALVES (2 * OP_HALVES)
#define STG_BYTES (STG_HALVES * 2)     // 20480
#define NSTG 4
#define GSMEM_BYTES (NSTG * STG_BYTES) // 81920

template <typename OutT>
__global__ void __launch_bounds__(256, 2)
gemm_f16(const __half* __restrict__ A, const __half* __restrict__ B,
         OutT* __restrict__ C, int Mreal, int N)
{
    extern __shared__ __half sm[];

    const int tid  = threadIdx.x;
    const int lane = tid & 31;
    const int warp = tid >> 5;          // 0..7
    const int wm   = warp >> 2;         // 0..1  (64-row tile)
    const int wn   = warp & 3;          // 0..3  (32-col tile)
    const int grp  = lane >> 2;
    const int tg   = lane & 3;

    const int m0 = blockIdx.y * BM;
    const int n0 = blockIdx.x * BN;
    const uint32_t smb = smem_u32(sm);

    // conflict-free fill: warp covers 8 rows x 64B; 8 warps -> 64 rows, 2 reps
    const int frow = warp * 8 + (lane & 7);     // 0..63 base
    const int fc   = (lane >> 3) << 3;          // halves: 0,8,16,24
    const __half*  ag0 = A + (size_t)(m0 + frow) * KDIM + fc;
    const __half*  bg0 = B + (size_t)(n0 + frow) * KDIM + fc;
    const uint32_t ad0 = smb + (uint32_t)((frow * RSH + fc) * 2);
    const uint32_t bd0 = ad0 + OP_HALVES * 2;

    // ldmatrix lane->address components
    const int l7 = lane & 7;
    const int lb = (lane >> 3) & 1;
    const int lt = lane >> 4;
    const uint32_t aL = smb +
        (uint32_t)(((wm * 64 + l7 + lb * 8) * RSH + lt * 8) * 2);
    const uint32_t bL = smb + (uint32_t)(OP_HALVES * 2) +
        (uint32_t)(((wn * 32 + l7 + lt * 8) * RSH + lb * 8) * 2);

    float acc[4][4][4];
    #pragma unroll
    for (int i = 0; i < 4; i++)
        #pragma unroll
        for (int j = 0; j < 4; j++)
            #pragma unroll
            for (int l = 0; l < 4; l++) acc[i][j][l] = 0.f;

    const int T = KDIM / BK;   // 16

    // prologue: stages 0..2
    #pragma unroll
    for (int s = 0; s < NSTG - 1; s++) {
        const uint32_t ad = ad0 + (uint32_t)(s * STG_BYTES);
        const uint32_t bd = bd0 + (uint32_t)(s * STG_BYTES);
        const __half* ag = ag0 + s * BK;
        const __half* bg = bg0 + s * BK;
        #pragma unroll
        for (int p = 0; p < 2; p++) {
            cp16(ad + (uint32_t)(p * 64 * RSH) * 2, ag + (size_t)p * 64 * KDIM);
            cp16(bd + (uint32_t)(p * 64 * RSH) * 2, bg + (size_t)p * 64 * KDIM);
        }
        CP_COMMIT();
    }

    for (int t = 0; t < T; ++t) {
        if (t < T - 2)      { CP_WAIT(2); }
        else if (t == T - 2){ CP_WAIT(1); }
        else                { CP_WAIT(0); }
        __syncthreads();

        // prefetch stage t+3 into buffer (t+3)&3 (last read at iter t-1)
        if (t + NSTG - 1 < T) {
            const int s = t + NSTG - 1;
            const uint32_t off = (uint32_t)((s & (NSTG - 1)) * STG_BYTES);
            const __half* ag = ag0 + s * BK;
            const __half* bg = bg0 + s * BK;
            #pragma unroll
            for (int p = 0; p < 2; p++) {
                cp16(ad0 + off + (uint32_t)(p * 64 * RSH) * 2, ag + (size_t)p * 64 * KDIM);
                cp16(bd0 + off + (uint32_t)(p * 64 * RSH) * 2, bg + (size_t)p * 64 * KDIM);
            }
            CP_COMMIT();
        }

        const uint32_t bufo = (uint32_t)((t & (NSTG - 1)) * STG_BYTES);
        const uint32_t aB = aL + bufo;
        const uint32_t bB = bL + bufo;
        #pragma unroll
        for (int ks = 0; ks < 2; ks++) {
            const uint32_t kkb = (uint32_t)(ks * 32);     // 16 halves
            unsigned af[4][4], bf[4][2];
            #pragma unroll
            for (int mt = 0; mt < 4; mt++)
                ldsm4(af[mt], aB + (uint32_t)(mt * 16 * RSH * 2) + kkb);
            #pragma unroll
            for (int np = 0; np < 2; np++) {
                unsigned r[4];
                ldsm4(r, bB + (uint32_t)(np * 16 * RSH * 2) + kkb);
                bf[2 * np][0] = r[0]; bf[2 * np][1] = r[1];
                bf[2 * np + 1][0] = r[2]; bf[2 * np + 1][1] = r[3];
            }
            #pragma unroll
            for (int mt = 0; mt < 4; mt++)
                #pragma unroll
                for (int nt = 0; nt < 4; nt++)
                    mma_f16(acc[mt][nt], af[mt], bf[nt]);
        }
    }

    #pragma unroll
    for (int mt = 0; mt < 4; mt++) {
        #pragma unroll
        for (int nt = 0; nt < 4; nt++) {
            int r0 = m0 + wm * 64 + mt * 16 + grp;
            int c  = n0 + wn * 32 + nt * 8 + tg * 2;
            if (r0 < Mreal)
                storeC(C, (size_t)r0 * N + c, acc[mt][nt][0], acc[mt][nt][1]);
            if (r0 + 8 < Mreal)
                storeC(C, (size_t)(r0 + 8) * N + c, acc[mt][nt][2], acc[mt][nt][3]);
        }
    }
}

// ------------------------------ prep kernels -------------------------------
__global__ void half_pad(const float* __restrict__ x, __half* __restrict__ xh,
                         long nreal, long ntot)
{
    long i = (long)blockIdx.x * blockDim.x + threadIdx.x;
    if (i < ntot) xh[i] = __float2half((i < nreal) ? x[i] : 0.f);
}

__global__ void transpose_half(const float* __restrict__ W, __half* __restrict__ WT,
                               int R, int Ccols)
{
    __shared__ float t[32][33];
    const int tx = threadIdx.x, ty = threadIdx.y;
    const int x = blockIdx.x * 32 + tx;
    #pragma unroll
    for (int j = 0; j < 4; j++) {
        int y = blockIdx.y * 32 + ty + j * 8;
        t[ty + j * 8][tx] = W[(size_t)y * Ccols + x];
    }
    __syncthreads();
    const int ox = blockIdx.y * 32 + tx;
    #pragma unroll
    for (int j = 0; j < 4; j++) {
        int oy = blockIdx.x * 32 + ty + j * 8;
        WT[(size_t)oy * R + ox] = __float2half(t[tx][ty + j * 8]);
    }
}

__global__ void zero_fill_h(__half* __restrict__ p, int n)
{
    int i = blockIdx.x * blockDim.x + threadIdx.x;
    if (i < n / 2) ((uint32_t*)p)[i] = 0u;
}

// ----------------------------- attention (tf32 HMMA, half I/O) -------------
#define QST 36
#define KST 36
#define VST 40
#define PST 60

__device__ __forceinline__ int div7(int v) { return (v * 37) >> 8; }  // exact 0..55

__global__ void __launch_bounds__(128)
attn_mma(const __half* __restrict__ qkv,
         const float* __restrict__ bias_table,
         __half* __restrict__ att)
{
    __shared__ float Qs[64 * QST];
    __shared__ float Ks[56 * KST];
    __shared__ float Vs[56 * VST];
    __shared__ float Ps[64 * PST];
    __shared__ float bs[176];
    __shared__ float inv[64];

    const int h  = blockIdx.x & 15;
    const int bw = blockIdx.x >> 4;
    const int tid  = threadIdx.x;
    const int lane = tid & 31;
    const int wm   = tid >> 5;
    const int grp  = lane >> 2;
    const int tg   = lane & 3;

    const __half* base = qkv + (size_t)bw * WIN * 1536 + h * 32;
    const float SCALE = 0.17677669529663687f;

    for (int l = tid; l < WIN * 4; l += 128) {
        int i = l >> 2, c = l & 3;
        const __half2* qrow = (const __half2*)(base + (size_t)i * 1536) + c * 4;
        const __half2* krow = (const __half2*)(base + (size_t)i * 1536 + 512) + c * 4;
        const __half2* vrow = (const __half2*)(base + (size_t)i * 1536 + 1024) + c * 4;
        #pragma unroll
        for (int q = 0; q < 4; q++) {
            float2 qf = __half22float2(qrow[q]);
            Qs[i * QST + c * 8 + 2 * q]     = tf32r(qf.x * SCALE);
            Qs[i * QST + c * 8 + 2 * q + 1] = tf32r(qf.y * SCALE);
            float2 kf = __half22float2(krow[q]);
            Ks[i * KST + c * 8 + 2 * q]     = kf.x;
            Ks[i * KST + c * 8 + 2 * q + 1] = kf.y;
            float2 vf = __half22float2(vrow[q]);
            Vs[i * VST + c * 8 + 2 * q]     = vf.x;
            Vs[i * VST + c * 8 + 2 * q + 1] = vf.y;
        }
    }
    const float4 z4 = make_float4(0.f, 0.f, 0.f, 0.f);
    for (int l = tid; l < 15 * 8; l += 128) {
        int i = WIN + (l >> 3), c = l & 7;
        *(float4*)(Qs + i * QST + c * 4) = z4;
        if (i < 56) {
            *(float4*)(Ks + i * KST + c * 4) = z4;
            *(float4*)(Vs + i * VST + c * 4) = z4;
        }
    }
    for (int l = tid; l < 169; l += 128) bs[l] = bias_table[l * HEADS + h];
    __syncthreads();

    const int i0 = wm * 16 + grp;
    const int i1 = i0 + 8;
    const int ri0 = div7(i0), ci0 = i0 - ri0 * 7;
    const int ri1 = div7(i1), ci1 = i1 - ri1 * 7;

    float c[7][4];
    #pragma unroll
    for (int nt = 0; nt < 7; nt++)
        #pragma unroll
        for (int l = 0; l < 4; l++) c[nt][l] = 0.f;

    #pragma unroll
    for (int ks = 0; ks < 4; ks++) {
        const int kk = ks * 8;
        unsigned a[4];
        a[0] = __float_as_uint(Qs[i0 * QST + kk + tg]);
        a[1] = __float_as_uint(Qs[i1 * QST + kk + tg]);
        a[2] = __float_as_uint(Qs[i0 * QST + kk + tg + 4]);
        a[3] = __float_as_uint(Qs[i1 * QST + kk + tg + 4]);
        #pragma unroll
        for (int nt = 0; nt < 7; nt++) {
            const int j = nt * 8 + grp;
            unsigned b[2];
            b[0] = __float_as_uint(Ks[j * KST + kk + tg]);
            b[1] = __float_as_uint(Ks[j * KST + kk + tg + 4]);
            mma_tf32(c[nt], a, b);
        }
    }

    float s01 = 0.f, s23 = 0.f;
    #pragma unroll
    for (int nt = 0; nt < 7; nt++) {
        const int j0 = nt * 8 + 2 * tg;
        const int j1 = j0 + 1;
        const int rj0 = div7(j0), cj0 = j0 - rj0 * 7;
        const int rj1 = div7(j1), cj1 = j1 - rj1 * 7;
        float e00 = 0.f, e01 = 0.f, e10 = 0.f, e11 = 0.f;
        if (j0 < WIN) {
            e00 = __expf(c[nt][0] + bs[(ri0 - rj0 + 6) * 13 + (ci0 - cj0 + 6)]);
            e10 = __expf(c[nt][2] + bs[(ri1 - rj0 + 6) * 13 + (ci1 - cj0 + 6)]);
        }
        if (j1 < WIN) {
            e01 = __expf(c[nt][1] + bs[(ri0 - rj1 + 6) * 13 + (ci0 - cj1 + 6)]);
            e11 = __expf(c[nt][3] + bs[(ri1 - rj1 + 6) * 13 + (ci1 - cj1 + 6)]);
        }
        s01 += e00 + e01;
        s23 += e10 + e11;
        *(float2*)(Ps + i0 * PST + j0) = make_float2(tf32r(e00), tf32r(e01));
        *(float2*)(Ps + i1 * PST + j0) = make_float2(tf32r(e10), tf32r(e11));
    }
    s01 += __shfl_xor_sync(0xFFFFFFFFu, s01, 1);
    s01 += __shfl_xor_sync(0xFFFFFFFFu, s01, 2);
    s23 += __shfl_xor_sync(0xFFFFFFFFu, s23, 1);
    s23 += __shfl_xor_sync(0xFFFFFFFFu, s23, 2);
    if (tg == 0) {
        inv[i0] = 1.f / s01;
        inv[i1] = 1.f / s23;
    }
    __syncwarp();

    float o[4][4];
    #pragma unroll
    for (int nt = 0; nt < 4; nt++)
        #pragma unroll
        for (int l = 0; l < 4; l++) o[nt][l] = 0.f;

    #pragma unroll
    for (int ks = 0; ks < 7; ks++) {
        const int kk = ks * 8;
        unsigned a[4];
        a[0] = __float_as_uint(Ps[i0 * PST + kk + tg]);
        a[1] = __float_as_uint(Ps[i1 * PST + kk + tg]);
        a[2] = __float_as_uint(Ps[i0 * PST + kk + tg + 4]);
        a[3] = __float_as_uint(Ps[i1 * PST + kk + tg + 4]);
        #pragma unroll
        for (int nt = 0; nt < 4; nt++) {
            unsigned b[2];
            b[0] = __float_as_uint(Vs[(kk + tg)     * VST + nt * 8 + grp]);
            b[1] = __float_as_uint(Vs[(kk + tg + 4) * VST + nt * 8 + grp]);
            mma_tf32(o[nt], a, b);
        }
    }

    const float v0 = inv[i0];
    const float v1 = inv[i1];
    __half* obase = att + (size_t)bw * WIN * 512 + h * 32;
    #pragma unroll
    for (int nt = 0; nt < 4; nt++) {
        const int d0 = nt * 8 + 2 * tg;
        if (i0 < WIN)
            *(__half2*)(obase + (size_t)i0 * 512 + d0) =
                __floats2half2_rn(o[nt][0] * v0, o[nt][1] * v0);
        if (i1 < WIN)
            *(__half2*)(obase + (size_t)i1 * 512 + d0) =
                __floats2half2_rn(o[nt][2] * v1, o[nt][3] * v1);
    }
}

// --------------------------------- launcher --------------------------------
extern "C" void kernel_launch(void* const* d_in, const int* in_sizes, int n_in,
                              void* d_out, int out_size)
{
    const float* x          = (const float*)d_in[0];
    const float* w_qkv      = (const float*)d_in[1];
    const float* bias_table = (const float*)d_in[2];
    const float* w_out      = (const float*)d_in[3];
    float* out = (float*)d_out;

    __half *qkvh, *atth, *xh, *wqkvT, *woutT;
    cudaGetSymbolAddress((void**)&qkvh,  g_qkvh);
    cudaGetSymbolAddress((void**)&atth,  g_atth);
    cudaGetSymbolAddress((void**)&xh,    g_xh);
    cudaGetSymbolAddress((void**)&wqkvT, g_wqkvT);
    cudaGetSymbolAddress((void**)&woutT, g_woutT);

    cudaFuncSetAttribute(gemm_f16<__half>,
                         cudaFuncAttributeMaxDynamicSharedMemorySize, GSMEM_BYTES);
    cudaFuncSetAttribute(gemm_f16<float>,
                         cudaFuncAttributeMaxDynamicSharedMemorySize, GSMEM_BYTES);

    const long nreal = (long)M_REAL * 512;
    const long ntot  = (long)M_PAD  * 512;

    // order keeps the ncu fixed capture slot on gemm K1
    half_pad<<<(int)((ntot + 255) / 256), 256>>>(x, xh, nreal, ntot);
    transpose_half<<<dim3(1536 / 32, 512 / 32), dim3(32, 8)>>>(w_qkv, wqkvT, 512, 1536);
    transpose_half<<<dim3(512 / 32, 512 / 32), dim3(32, 8)>>>(w_out, woutT, 512, 512);

    // K1: qkvh = xh @ wqkvT^T
    gemm_f16<__half><<<dim3(1536 / BN, M_PAD / BM), 256, GSMEM_BYTES>>>(
        xh, wqkvT, qkvh, M_REAL, 1536);

    zero_fill_h<<<(64 * 512 / 2 + 255) / 256, 256>>>(atth + nreal, 64 * 512);

    // K2: attention
    attn_mma<<<NWIN * HEADS, 128>>>(qkvh, bias_table, atth);

    // K3: out = atth @ woutT^T
    gemm_f16<float><<<dim3(512 / BN, M_PAD / BM), 256, GSMEM_BYTES>>>(
        atth, woutT, out, M_REAL, 512);
}

// round 14
// speedup vs baseline: 1.2439x; 1.2439x over previous
#include <cuda_runtime.h>
#include <cuda_fp16.h>
#include <cstdint>

// ---------------------------------------------------------------------------
// MultiAxisAttention (Swin window attention) — fp16 HMMA everywhere.
// R14: GEMM = R12 verbatim (128x128, 4 warps 64x64, NSTG=3, 3 CTAs/SM).
//      Attention rewritten in pure fp16 m16n8k16 (no cvt, raw half smem).
//      half_pad vectorized x8.
// ---------------------------------------------------------------------------

#define M_REAL 153664            // 16*196*49
#define M_PAD  153728            // 1201*128
#define NWIN   3136
#define HEADS  16
#define WIN    49
#define KDIM   512

__device__ __half g_qkvh[236027904];   // M_REAL*1536
__device__ __half g_atth[78708736];    // M_PAD*512 (pad rows zeroed)
__device__ __half g_xh  [78708736];    // M_PAD*512 (pad rows zeroed)
__device__ __half g_wqkvT[786432];     // [1536][512]
__device__ __half g_woutT[262144];     // [512][512]

// ------------------------------ helpers -----------------------------------
__device__ __forceinline__ uint32_t smem_u32(const void* p) {
    uint32_t a;
    asm("{ .reg .u64 t; cvta.to.shared.u64 t, %1; cvt.u32.u64 %0, t; }"
        : "=r"(a) : "l"(p));
    return a;
}
__device__ __forceinline__ void cp16(uint32_t dst, const void* src) {
    asm volatile("cp.async.cg.shared.global [%0], [%1], 16;\n"
                 :: "r"(dst), "l"(src));
}
#define CP_COMMIT() asm volatile("cp.async.commit_group;\n" ::: "memory")
#define CP_WAIT(n)  asm volatile("cp.async.wait_group %0;\n" :: "n"(n) : "memory")

__device__ __forceinline__ void ldsm4(unsigned* r, uint32_t a) {
    asm volatile("ldmatrix.sync.aligned.m8n8.x4.shared.b16 {%0,%1,%2,%3}, [%4];"
                 : "=r"(r[0]), "=r"(r[1]), "=r"(r[2]), "=r"(r[3]) : "r"(a));
}
__device__ __forceinline__ void mma_f16(float* d, const unsigned* a, const unsigned* b) {
    asm volatile(
        "mma.sync.aligned.m16n8k16.row.col.f32.f16.f16.f32 "
        "{%0,%1,%2,%3}, {%4,%5,%6,%7}, {%8,%9}, {%0,%1,%2,%3};\n"
        : "+f"(d[0]), "+f"(d[1]), "+f"(d[2]), "+f"(d[3])
        : "r"(a[0]), "r"(a[1]), "r"(a[2]), "r"(a[3]),
          "r"(b[0]), "r"(b[1]));
}

__device__ __forceinline__ void storeC(float* C, size_t idx, float a, float b) {
    *(float2*)(C + idx) = make_float2(a, b);
}
__device__ __forceinline__ void storeC(__half* C, size_t idx, float a, float b) {
    *(__half2*)(C + idx) = __floats2half2_rn(a, b);
}

// ----------------------------- GEMM (fp16) — R12 verbatim ------------------
#define BM 128
#define BN 128
#define BK 32
#define RSH 40
#define OP_HALVES (128 * RSH)          // 5120 per operand per stage
#define STG_HALVES (2 * OP_HALVES)
#define STG_BYTES (STG_HALVES * 2)     // 20480
#define NSTG 3
#define GSMEM_BYTES (NSTG * STG_BYTES) // 61440

template <typename OutT>
__global__ void __launch_bounds__(128, 3)
gemm_f16(const __half* __restrict__ A, const __half* __restrict__ B,
         OutT* __restrict__ C, int Mreal, int N)
{
    extern __shared__ __half sm[];

    const int tid  = threadIdx.x;
    const int lane = tid & 31;
    const int warp = tid >> 5;          // 0..3
    const int wm   = warp >> 1;
    const int wn   = warp & 1;
    const int grp  = lane >> 2;
    const int tg   = lane & 3;

    const int m0 = blockIdx.y * BM;
    const int n0 = blockIdx.x * BN;
    const uint32_t smb = smem_u32(sm);

    const int frow = warp * 8 + (lane & 7);
    const int fc   = (lane >> 3) << 3;
    const __half*  ag0 = A + (size_t)(m0 + frow) * KDIM + fc;
    const __half*  bg0 = B + (size_t)(n0 + frow) * KDIM + fc;
    const uint32_t ad0 = smb + (uint32_t)((frow * RSH + fc) * 2);
    const uint32_t bd0 = ad0 + OP_HALVES * 2;

    const int l7 = lane & 7;
    const int lb = (lane >> 3) & 1;
    const int lt = lane >> 4;
    const uint32_t aL = smb +
        (uint32_t)(((wm * 64 + l7 + lb * 8) * RSH + lt * 8) * 2);
    const uint32_t bL = smb + (uint32_t)(OP_HALVES * 2) +
        (uint32_t)(((wn * 64 + l7 + lt * 8) * RSH + lb * 8) * 2);

    float acc[4][8][4];
    #pragma unroll
    for (int i = 0; i < 4; i++)
        #pragma unroll
        for (int j = 0; j < 8; j++)
            #pragma unroll
            for (int l = 0; l < 4; l++) acc[i][j][l] = 0.f;

    const int T = KDIM / BK;   // 16

    #pragma unroll
    for (int s = 0; s < NSTG - 1; s++) {
        const uint32_t ad = ad0 + (uint32_t)(s * STG_BYTES);
        const uint32_t bd = bd0 + (uint32_t)(s * STG_BYTES);
        const __half* ag = ag0 + s * BK;
        const __half* bg = bg0 + s * BK;
        #pragma unroll
        for (int p = 0; p < 4; p++) {
            cp16(ad + (uint32_t)(p * 32 * RSH) * 2, ag + (size_t)p * 32 * KDIM);
            cp16(bd + (uint32_t)(p * 32 * RSH) * 2, bg + (size_t)p * 32 * KDIM);
        }
        CP_COMMIT();
    }

    int bc = 0;
    int pb = 2;
    for (int t = 0; t < T; ++t) {
        if (t < T - 1) { CP_WAIT(1); } else { CP_WAIT(0); }
        __syncthreads();

        if (t + NSTG - 1 < T) {
            const int s = t + NSTG - 1;
            const uint32_t off = (uint32_t)(pb * STG_BYTES);
            const __half* ag = ag0 + s * BK;
            const __half* bg = bg0 + s * BK;
            #pragma unroll
            for (int p = 0; p < 4; p++) {
                cp16(ad0 + off + (uint32_t)(p * 32 * RSH) * 2, ag + (size_t)p * 32 * KDIM);
                cp16(bd0 + off + (uint32_t)(p * 32 * RSH) * 2, bg + (size_t)p * 32 * KDIM);
            }
            CP_COMMIT();
        }

        const uint32_t bufo = (uint32_t)(bc * STG_BYTES);
        const uint32_t aB = aL + bufo;
        const uint32_t bB = bL + bufo;
        #pragma unroll
        for (int ks = 0; ks < 2; ks++) {
            const uint32_t kkb = (uint32_t)(ks * 32);
            unsigned af[4][4], bf[8][2];
            #pragma unroll
            for (int mt = 0; mt < 4; mt++)
                ldsm4(af[mt], aB + (uint32_t)(mt * 16 * RSH * 2) + kkb);
            #pragma unroll
            for (int np = 0; np < 4; np++) {
                unsigned r[4];
                ldsm4(r, bB + (uint32_t)(np * 16 * RSH * 2) + kkb);
                bf[2 * np][0] = r[0]; bf[2 * np][1] = r[1];
                bf[2 * np + 1][0] = r[2]; bf[2 * np + 1][1] = r[3];
            }
            #pragma unroll
            for (int mt = 0; mt < 4; mt++)
                #pragma unroll
                for (int nt = 0; nt < 8; nt++)
                    mma_f16(acc[mt][nt], af[mt], bf[nt]);
        }

        bc = (bc == 2) ? 0 : bc + 1;
        pb = (pb == 2) ? 0 : pb + 1;
    }

    #pragma unroll
    for (int mt = 0; mt < 4; mt++) {
        #pragma unroll
        for (int nt = 0; nt < 8; nt++) {
            int r0 = m0 + wm * 64 + mt * 16 + grp;
            int c  = n0 + wn * 64 + nt * 8 + tg * 2;
            if (r0 < Mreal)
                storeC(C, (size_t)r0 * N + c, acc[mt][nt][0], acc[mt][nt][1]);
            if (r0 + 8 < Mreal)
                storeC(C, (size_t)(r0 + 8) * N + c, acc[mt][nt][2], acc[mt][nt][3]);
        }
    }
}

// ------------------------------ prep kernels -------------------------------
// vectorized: 8 elems per thread (2x float4 -> uint4 of halves)
__global__ void half_pad8(const float4* __restrict__ x, uint4* __restrict__ xh,
                          long n8real, long n8tot)
{
    long i = (long)blockIdx.x * blockDim.x + threadIdx.x;
    if (i >= n8tot) return;
    uint4 o = make_uint4(0u, 0u, 0u, 0u);
    if (i < n8real) {
        float4 a = x[2 * i];
        float4 b = x[2 * i + 1];
        __half2 h0 = __floats2half2_rn(a.x, a.y);
        __half2 h1 = __floats2half2_rn(a.z, a.w);
        __half2 h2 = __floats2half2_rn(b.x, b.y);
        __half2 h3 = __floats2half2_rn(b.z, b.w);
        o.x = *(unsigned*)&h0; o.y = *(unsigned*)&h1;
        o.z = *(unsigned*)&h2; o.w = *(unsigned*)&h3;
    }
    xh[i] = o;
}

__global__ void transpose_half(const float* __restrict__ W, __half* __restrict__ WT,
                               int R, int Ccols)
{
    __shared__ float t[32][33];
    const int tx = threadIdx.x, ty = threadIdx.y;
    const int x = blockIdx.x * 32 + tx;
    #pragma unroll
    for (int j = 0; j < 4; j++) {
        int y = blockIdx.y * 32 + ty + j * 8;
        t[ty + j * 8][tx] = W[(size_t)y * Ccols + x];
    }
    __syncthreads();
    const int ox = blockIdx.y * 32 + tx;
    #pragma unroll
    for (int j = 0; j < 4; j++) {
        int oy = blockIdx.x * 32 + ty + j * 8;
        WT[(size_t)oy * R + ox] = __float2half(t[tx][ty + j * 8]);
    }
}

__global__ void zero_fill_h(__half* __restrict__ p, int n)
{
    int i = blockIdx.x * blockDim.x + threadIdx.x;
    if (i < n / 2) ((uint32_t*)p)[i] = 0u;
}

// ----------------------------- attention (fp16 HMMA) -----------------------
// one CTA per (window, head); 128 threads (4 warps, warp = 16 query rows).
// QK^T [64x56] (k=32) and PV [64x32] (k=64, zero-padded) on m16n8k16.f16.
// Raw half smem (no conversions); SCALE applied post-MMA; V stored transposed.
#define QSH 40    // Qs  [64][40]h
#define KSH 40    // Ks  [56][40]h
#define VSH 72    // VsT [32][72]h  (cols j 0..63 used)
#define PSH 72    // Ps  [64][72]h  (cols j 0..63 used)

__device__ __forceinline__ int div7(int v) { return (v * 37) >> 8; }  // exact 0..55

__global__ void __launch_bounds__(128)
attn_f16(const __half* __restrict__ qkv,
         const float* __restrict__ bias_table,
         __half* __restrict__ att)
{
    __shared__ __half Qs[64 * QSH];
    __shared__ __half Ks[56 * KSH];
    __shared__ __half VsT[32 * VSH];
    __shared__ __half Ps[64 * PSH];
    __shared__ float bs[176];
    __shared__ float inv[64];

    const int h  = blockIdx.x & 15;
    const int bw = blockIdx.x >> 4;
    const int tid  = threadIdx.x;
    const int lane = tid & 31;
    const int wm   = tid >> 5;
    const int grp  = lane >> 2;
    const int tg   = lane & 3;

    const __half* base = qkv + (size_t)bw * WIN * 1536 + h * 32;
    const float SCALE = 0.17677669529663687f;

    // ---- fills: Q/K raw 16B chunks; V transposed (scalar) ----
    for (int l = tid; l < WIN * 4; l += 128) {
        int i = l >> 2, c = l & 3;
        const uint4* qrow = (const uint4*)(base + (size_t)i * 1536);
        *(uint4*)(Qs + i * QSH + c * 8) = qrow[c];
        *(uint4*)(Ks + i * KSH + c * 8) =
            *((const uint4*)(base + (size_t)i * 1536 + 512) + c);
        const __half2* vrow = (const __half2*)(base + (size_t)i * 1536 + 1024);
        #pragma unroll
        for (int q = 0; q < 4; q++) {
            __half2 v2 = vrow[c * 4 + q];
            int d = c * 8 + 2 * q;
            VsT[d * VSH + i]       = __low2half(v2);
            VsT[(d + 1) * VSH + i] = __high2half(v2);
        }
    }
    // ---- zero pads ----
    const uint4 z4 = make_uint4(0u, 0u, 0u, 0u);
    for (int l = tid; l < 75; l += 128) {         // Q rows 49..63
        int r = 49 + l / 5, c = l % 5;
        *(uint4*)(Qs + r * QSH + c * 8) = z4;
    }
    for (int l = tid; l < 35; l += 128) {         // K rows 49..55
        int r = 49 + l / 5, c = l % 5;
        *(uint4*)(Ks + r * KSH + c * 8) = z4;
    }
    for (int l = tid; l < 480; l += 128) {        // VsT cols 49..63
        int d = l / 15, j = 49 + l % 15;
        VsT[d * VSH + j] = __float2half(0.f);
    }
    {                                             // Ps cols 56..71 (all rows)
        int r = tid >> 1, p = tid & 1;
        *(uint4*)(Ps + r * PSH + 56 + p * 8) = z4;
    }
    for (int l = tid; l < 169; l += 128) bs[l] = bias_table[l * HEADS + h];
    __syncthreads();

    const int i0 = wm * 16 + grp;
    const int i1 = i0 + 8;
    const int ri0 = div7(i0), ci0 = i0 - ri0 * 7;
    const int ri1 = div7(i1), ci1 = i1 - ri1 * 7;

    // ---- QK^T: k=32, 2 k16-steps, 7 n-tiles ----
    float c[7][4];
    #pragma unroll
    for (int nt = 0; nt < 7; nt++)
        #pragma unroll
        for (int l = 0; l < 4; l++) c[nt][l] = 0.f;

    #pragma unroll
    for (int ks = 0; ks < 2; ks++) {
        const int kk = ks * 16;
        unsigned a[4];
        a[0] = *(const unsigned*)(Qs + i0 * QSH + kk + 2 * tg);
        a[1] = *(const unsigned*)(Qs + i1 * QSH + kk + 2 * tg);
        a[2] = *(const unsigned*)(Qs + i0 * QSH + kk + 8 + 2 * tg);
        a[3] = *(const unsigned*)(Qs + i1 * QSH + kk + 8 + 2 * tg);
        #pragma unroll
        for (int nt = 0; nt < 7; nt++) {
            const int j = nt * 8 + grp;
            unsigned b[2];
            b[0] = *(const unsigned*)(Ks + j * KSH + kk + 2 * tg);
            b[1] = *(const unsigned*)(Ks + j * KSH + kk + 8 + 2 * tg);
            mma_f16(c[nt], a, b);
        }
    }

    // ---- softmax numerators -> Ps (half2), row sums via tg-butterfly ----
    float s01 = 0.f, s23 = 0.f;
    #pragma unroll
    for (int nt = 0; nt < 7; nt++) {
        const int j0 = nt * 8 + 2 * tg;
        const int j1 = j0 + 1;
        const int rj0 = div7(j0), cj0 = j0 - rj0 * 7;
        const int rj1 = div7(j1), cj1 = j1 - rj1 * 7;
        float e00 = 0.f, e01 = 0.f, e10 = 0.f, e11 = 0.f;
        if (j0 < WIN) {
            e00 = __expf(c[nt][0] * SCALE + bs[(ri0 - rj0 + 6) * 13 + (ci0 - cj0 + 6)]);
            e10 = __expf(c[nt][2] * SCALE + bs[(ri1 - rj0 + 6) * 13 + (ci1 - cj0 + 6)]);
        }
        if (j1 < WIN) {
            e01 = __expf(c[nt][1] * SCALE + bs[(ri0 - rj1 + 6) * 13 + (ci0 - cj1 + 6)]);
            e11 = __expf(c[nt][3] * SCALE + bs[(ri1 - rj1 + 6) * 13 + (ci1 - cj1 + 6)]);
        }
        s01 += e00 + e01;
        s23 += e10 + e11;
        *(__half2*)(Ps + i0 * PSH + j0) = __floats2half2_rn(e00, e01);
        *(__half2*)(Ps + i1 * PSH + j0) = __floats2half2_rn(e10, e11);
    }
    s01 += __shfl_xor_sync(0xFFFFFFFFu, s01, 1);
    s01 += __shfl_xor_sync(0xFFFFFFFFu, s01, 2);
    s23 += __shfl_xor_sync(0xFFFFFFFFu, s23, 1);
    s23 += __shfl_xor_sync(0xFFFFFFFFu, s23, 2);
    if (tg == 0) {
        inv[i0] = 1.f / s01;
        inv[i1] = 1.f / s23;
    }
    __syncwarp();      // P rows + inv are warp-local

    // ---- PV: k=64 (padded), 4 k16-steps, 4 n-tiles ----
    float o[4][4];
    #pragma unroll
    for (int nt = 0; nt < 4; nt++)
        #pragma unroll
        for (int l = 0; l < 4; l++) o[nt][l] = 0.f;

    #pragma unroll
    for (int ks = 0; ks < 4; ks++) {
        const int kk = ks * 16;
        unsigned a[4];
        a[0] = *(const unsigned*)(Ps + i0 * PSH + kk + 2 * tg);
        a[1] = *(const unsigned*)(Ps + i1 * PSH + kk + 2 * tg);
        a[2] = *(const unsigned*)(Ps + i0 * PSH + kk + 8 + 2 * tg);
        a[3] = *(const unsigned*)(Ps + i1 * PSH + kk + 8 + 2 * tg);
        #pragma unroll
        for (int nt = 0; nt < 4; nt++) {
            const int n = nt * 8 + grp;
            unsigned b[2];
            b[0] = *(const unsigned*)(VsT + n * VSH + kk + 2 * tg);
            b[1] = *(const unsigned*)(VsT + n * VSH + kk + 8 + 2 * tg);
            mma_f16(o[nt], a, b);
        }
    }

    const float v0 = inv[i0];
    const float v1 = inv[i1];
    __half* obase = att + (size_t)bw * WIN * 512 + h * 32;
    #pragma unroll
    for (int nt = 0; nt < 4; nt++) {
        const int d0 = nt * 8 + 2 * tg;
        if (i0 < WIN)
            *(__half2*)(obase + (size_t)i0 * 512 + d0) =
                __floats2half2_rn(o[nt][0] * v0, o[nt][1] * v0);
        if (i1 < WIN)
            *(__half2*)(obase + (size_t)i1 * 512 + d0) =
                __floats2half2_rn(o[nt][2] * v1, o[nt][3] * v1);
    }
}

// --------------------------------- launcher --------------------------------
extern "C" void kernel_launch(void* const* d_in, const int* in_sizes, int n_in,
                              void* d_out, int out_size)
{
    const float* x          = (const float*)d_in[0];
    const float* w_qkv      = (const float*)d_in[1];
    const float* bias_table = (const float*)d_in[2];
    const float* w_out      = (const float*)d_in[3];
    float* out = (float*)d_out;

    __half *qkvh, *atth, *xh, *wqkvT, *woutT;
    cudaGetSymbolAddress((void**)&qkvh,  g_qkvh);
    cudaGetSymbolAddress((void**)&atth,  g_atth);
    cudaGetSymbolAddress((void**)&xh,    g_xh);
    cudaGetSymbolAddress((void**)&wqkvT, g_wqkvT);
    cudaGetSymbolAddress((void**)&woutT, g_woutT);

    cudaFuncSetAttribute(gemm_f16<__half>,
                         cudaFuncAttributeMaxDynamicSharedMemorySize, GSMEM_BYTES);
    cudaFuncSetAttribute(gemm_f16<float>,
                         cudaFuncAttributeMaxDynamicSharedMemorySize, GSMEM_BYTES);

    const long nreal = (long)M_REAL * 512;
    const long ntot  = (long)M_PAD  * 512;
    const long n8real = nreal / 8;
    const long n8tot  = ntot / 8;

    // order keeps the ncu fixed capture slot on gemm K1
    half_pad8<<<(int)((n8tot + 255) / 256), 256>>>(
        (const float4*)x, (uint4*)xh, n8real, n8tot);
    transpose_half<<<dim3(1536 / 32, 512 / 32), dim3(32, 8)>>>(w_qkv, wqkvT, 512, 1536);
    transpose_half<<<dim3(512 / 32, 512 / 32), dim3(32, 8)>>>(w_out, woutT, 512, 512);

    // K1: qkvh = xh @ wqkvT^T
    gemm_f16<__half><<<dim3(1536 / BN, M_PAD / BM), 128, GSMEM_BYTES>>>(
        xh, wqkvT, qkvh, M_REAL, 1536);

    zero_fill_h<<<(64 * 512 / 2 + 255) / 256, 256>>>(atth + nreal, 64 * 512);

    // K2: attention (pure fp16 tensor-core)
    attn_f16<<<NWIN * HEADS, 128>>>(qkvh, bias_table, atth);

    // K3: out = atth @ woutT^T
    gemm_f16<float><<<dim3(512 / BN, M_PAD / BM), 128, GSMEM_BYTES>>>(
        atth, woutT, out, M_REAL, 512);
}

// round 15
// speedup vs baseline: 1.2772x; 1.0268x over previous
#include <cuda_runtime.h>
#include <cuda_fp16.h>
#include <cstdint>

// ---------------------------------------------------------------------------
// MultiAxisAttention (Swin window attention) — fp16 HMMA everywhere.
// R15: GEMM = R12/R14 verbatim. Attention fragment loads via ldmatrix.x4
//      (non-trans for Q/K/P, .trans for V), V stored row-major with
//      conflict-free vectorized fill (kills the scalar transposed STS).
// ---------------------------------------------------------------------------

#define M_REAL 153664            // 16*196*49
#define M_PAD  153728            // 1201*128
#define NWIN   3136
#define HEADS  16
#define WIN    49
#define KDIM   512

__device__ __half g_qkvh[236027904];   // M_REAL*1536
__device__ __half g_atth[78708736];    // M_PAD*512 (pad rows zeroed)
__device__ __half g_xh  [78708736];    // M_PAD*512 (pad rows zeroed)
__device__ __half g_wqkvT[786432];     // [1536][512]
__device__ __half g_woutT[262144];     // [512][512]

// ------------------------------ helpers -----------------------------------
__device__ __forceinline__ uint32_t smem_u32(const void* p) {
    uint32_t a;
    asm("{ .reg .u64 t; cvta.to.shared.u64 t, %1; cvt.u32.u64 %0, t; }"
        : "=r"(a) : "l"(p));
    return a;
}
__device__ __forceinline__ void cp16(uint32_t dst, const void* src) {
    asm volatile("cp.async.cg.shared.global [%0], [%1], 16;\n"
                 :: "r"(dst), "l"(src));
}
#define CP_COMMIT() asm volatile("cp.async.commit_group;\n" ::: "memory")
#define CP_WAIT(n)  asm volatile("cp.async.wait_group %0;\n" :: "n"(n) : "memory")

__device__ __forceinline__ void ldsm4(unsigned* r, uint32_t a) {
    asm volatile("ldmatrix.sync.aligned.m8n8.x4.shared.b16 {%0,%1,%2,%3}, [%4];"
                 : "=r"(r[0]), "=r"(r[1]), "=r"(r[2]), "=r"(r[3]) : "r"(a));
}
__device__ __forceinline__ void ldsm4t(unsigned* r, uint32_t a) {
    asm volatile("ldmatrix.sync.aligned.m8n8.x4.trans.shared.b16 {%0,%1,%2,%3}, [%4];"
                 : "=r"(r[0]), "=r"(r[1]), "=r"(r[2]), "=r"(r[3]) : "r"(a));
}
__device__ __forceinline__ void mma_f16(float* d, const unsigned* a, const unsigned* b) {
    asm volatile(
        "mma.sync.aligned.m16n8k16.row.col.f32.f16.f16.f32 "
        "{%0,%1,%2,%3}, {%4,%5,%6,%7}, {%8,%9}, {%0,%1,%2,%3};\n"
        : "+f"(d[0]), "+f"(d[1]), "+f"(d[2]), "+f"(d[3])
        : "r"(a[0]), "r"(a[1]), "r"(a[2]), "r"(a[3]),
          "r"(b[0]), "r"(b[1]));
}

__device__ __forceinline__ void storeC(float* C, size_t idx, float a, float b) {
    *(float2*)(C + idx) = make_float2(a, b);
}
__device__ __forceinline__ void storeC(__half* C, size_t idx, float a, float b) {
    *(__half2*)(C + idx) = __floats2half2_rn(a, b);
}

// ----------------------------- GEMM (fp16) — R12 verbatim ------------------
#define BM 128
#define BN 128
#define BK 32
#define RSH 40
#define OP_HALVES (128 * RSH)          // 5120 per operand per stage
#define STG_HALVES (2 * OP_HALVES)
#define STG_BYTES (STG_HALVES * 2)     // 20480
#define NSTG 3
#define GSMEM_BYTES (NSTG * STG_BYTES) // 61440

template <typename OutT>
__global__ void __launch_bounds__(128, 3)
gemm_f16(const __half* __restrict__ A, const __half* __restrict__ B,
         OutT* __restrict__ C, int Mreal, int N)
{
    extern __shared__ __half sm[];

    const int tid  = threadIdx.x;
    const int lane = tid & 31;
    const int warp = tid >> 5;          // 0..3
    const int wm   = warp >> 1;
    const int wn   = warp & 1;
    const int grp  = lane >> 2;
    const int tg   = lane & 3;

    const int m0 = blockIdx.y * BM;
    const int n0 = blockIdx.x * BN;
    const uint32_t smb = smem_u32(sm);

    const int frow = warp * 8 + (lane & 7);
    const int fc   = (lane >> 3) << 3;
    const __half*  ag0 = A + (size_t)(m0 + frow) * KDIM + fc;
    const __half*  bg0 = B + (size_t)(n0 + frow) * KDIM + fc;
    const uint32_t ad0 = smb + (uint32_t)((frow * RSH + fc) * 2);
    const uint32_t bd0 = ad0 + OP_HALVES * 2;

    const int l7 = lane & 7;
    const int lb = (lane >> 3) & 1;
    const int lt = lane >> 4;
    const uint32_t aL = smb +
        (uint32_t)(((wm * 64 + l7 + lb * 8) * RSH + lt * 8) * 2);
    const uint32_t bL = smb + (uint32_t)(OP_HALVES * 2) +
        (uint32_t)(((wn * 64 + l7 + lt * 8) * RSH + lb * 8) * 2);

    float acc[4][8][4];
    #pragma unroll
    for (int i = 0; i < 4; i++)
        #pragma unroll
        for (int j = 0; j < 8; j++)
            #pragma unroll
            for (int l = 0; l < 4; l++) acc[i][j][l] = 0.f;

    const int T = KDIM / BK;   // 16

    #pragma unroll
    for (int s = 0; s < NSTG - 1; s++) {
        const uint32_t ad = ad0 + (uint32_t)(s * STG_BYTES);
        const uint32_t bd = bd0 + (uint32_t)(s * STG_BYTES);
        const __half* ag = ag0 + s * BK;
        const __half* bg = bg0 + s * BK;
        #pragma unroll
        for (int p = 0; p < 4; p++) {
            cp16(ad + (uint32_t)(p * 32 * RSH) * 2, ag + (size_t)p * 32 * KDIM);
            cp16(bd + (uint32_t)(p * 32 * RSH) * 2, bg + (size_t)p * 32 * KDIM);
        }
        CP_COMMIT();
    }

    int bc = 0;
    int pb = 2;
    for (int t = 0; t < T; ++t) {
        if (t < T - 1) { CP_WAIT(1); } else { CP_WAIT(0); }
        __syncthreads();

        if (t + NSTG - 1 < T) {
            const int s = t + NSTG - 1;
            const uint32_t off = (uint32_t)(pb * STG_BYTES);
            const __half* ag = ag0 + s * BK;
            const __half* bg = bg0 + s * BK;
            #pragma unroll
            for (int p = 0; p < 4; p++) {
                cp16(ad0 + off + (uint32_t)(p * 32 * RSH) * 2, ag + (size_t)p * 32 * KDIM);
                cp16(bd0 + off + (uint32_t)(p * 32 * RSH) * 2, bg + (size_t)p * 32 * KDIM);
            }
            CP_COMMIT();
        }

        const uint32_t bufo = (uint32_t)(bc * STG_BYTES);
        const uint32_t aB = aL + bufo;
        const uint32_t bB = bL + bufo;
        #pragma unroll
        for (int ks = 0; ks < 2; ks++) {
            const uint32_t kkb = (uint32_t)(ks * 32);
            unsigned af[4][4], bf[8][2];
            #pragma unroll
            for (int mt = 0; mt < 4; mt++)
                ldsm4(af[mt], aB + (uint32_t)(mt * 16 * RSH * 2) + kkb);
            #pragma unroll
            for (int np = 0; np < 4; np++) {
                unsigned r[4];
                ldsm4(r, bB + (uint32_t)(np * 16 * RSH * 2) + kkb);
                bf[2 * np][0] = r[0]; bf[2 * np][1] = r[1];
                bf[2 * np + 1][0] = r[2]; bf[2 * np + 1][1] = r[3];
            }
            #pragma unroll
            for (int mt = 0; mt < 4; mt++)
                #pragma unroll
                for (int nt = 0; nt < 8; nt++)
                    mma_f16(acc[mt][nt], af[mt], bf[nt]);
        }

        bc = (bc == 2) ? 0 : bc + 1;
        pb = (pb == 2) ? 0 : pb + 1;
    }

    #pragma unroll
    for (int mt = 0; mt < 4; mt++) {
        #pragma unroll
        for (int nt = 0; nt < 8; nt++) {
            int r0 = m0 + wm * 64 + mt * 16 + grp;
            int c  = n0 + wn * 64 + nt * 8 + tg * 2;
            if (r0 < Mreal)
                storeC(C, (size_t)r0 * N + c, acc[mt][nt][0], acc[mt][nt][1]);
            if (r0 + 8 < Mreal)
                storeC(C, (size_t)(r0 + 8) * N + c, acc[mt][nt][2], acc[mt][nt][3]);
        }
    }
}

// ------------------------------ prep kernels -------------------------------
__global__ void half_pad8(const float4* __restrict__ x, uint4* __restrict__ xh,
                          long n8real, long n8tot)
{
    long i = (long)blockIdx.x * blockDim.x + threadIdx.x;
    if (i >= n8tot) return;
    uint4 o = make_uint4(0u, 0u, 0u, 0u);
    if (i < n8real) {
        float4 a = x[2 * i];
        float4 b = x[2 * i + 1];
        __half2 h0 = __floats2half2_rn(a.x, a.y);
        __half2 h1 = __floats2half2_rn(a.z, a.w);
        __half2 h2 = __floats2half2_rn(b.x, b.y);
        __half2 h3 = __floats2half2_rn(b.z, b.w);
        o.x = *(unsigned*)&h0; o.y = *(unsigned*)&h1;
        o.z = *(unsigned*)&h2; o.w = *(unsigned*)&h3;
    }
    xh[i] = o;
}

__global__ void transpose_half(const float* __restrict__ W, __half* __restrict__ WT,
                               int R, int Ccols)
{
    __shared__ float t[32][33];
    const int tx = threadIdx.x, ty = threadIdx.y;
    const int x = blockIdx.x * 32 + tx;
    #pragma unroll
    for (int j = 0; j < 4; j++) {
        int y = blockIdx.y * 32 + ty + j * 8;
        t[ty + j * 8][tx] = W[(size_t)y * Ccols + x];
    }
    __syncthreads();
    const int ox = blockIdx.y * 32 + tx;
    #pragma unroll
    for (int j = 0; j < 4; j++) {
        int oy = blockIdx.x * 32 + ty + j * 8;
        WT[(size_t)oy * R + ox] = __float2half(t[tx][ty + j * 8]);
    }
}

__global__ void zero_fill_h(__half* __restrict__ p, int n)
{
    int i = blockIdx.x * blockDim.x + threadIdx.x;
    if (i < n / 2) ((uint32_t*)p)[i] = 0u;
}

// ----------------------------- attention (fp16 HMMA, ldmatrix) -------------
// one CTA per (window, head); 128 threads (4 warps, warp = 16 query rows).
// QK^T [64x56] (k=32) and PV [64x32] (k=64) on m16n8k16.f16.
// All fragments via ldmatrix.x4 (V via .trans on row-major Vs).
#define QSH 40    // Qs [64][40]h
#define KSH 40    // Ks [64][40]h (rows 49..63 zero)
#define VSH 40    // Vs [64][40]h (rows 49..63 zero)
#define PSH 72    // Ps [64][72]h (cols j 0..63 used)

__device__ __forceinline__ int div7(int v) { return (v * 37) >> 8; }  // exact 0..55

__global__ void __launch_bounds__(128)
attn_f16(const __half* __restrict__ qkv,
         const float* __restrict__ bias_table,
         __half* __restrict__ att)
{
    __shared__ __half Qs[64 * QSH];
    __shared__ __half Ks[64 * KSH];
    __shared__ __half Vs[64 * VSH];
    __shared__ __half Ps[64 * PSH];
    __shared__ float bs[176];
    __shared__ float inv[64];

    const int h  = blockIdx.x & 15;
    const int bw = blockIdx.x >> 4;
    const int tid  = threadIdx.x;
    const int lane = tid & 31;
    const int wm   = tid >> 5;
    const int grp  = lane >> 2;
    const int tg   = lane & 3;

    const __half* base = qkv + (size_t)bw * WIN * 1536 + h * 32;
    const float SCALE = 0.17677669529663687f;

    // ---- fills: Q/K/V raw 16B chunks (conflict classes (5i+c)%8, 4x) ----
    for (int l = tid; l < WIN * 4; l += 128) {
        int i = l >> 2, c = l & 3;
        const uint4* row = (const uint4*)(base + (size_t)i * 1536);
        *(uint4*)(Qs + i * QSH + c * 8) = row[c];
        *(uint4*)(Ks + i * KSH + c * 8) =
            *((const uint4*)(base + (size_t)i * 1536 + 512) + c);
        *(uint4*)(Vs + i * VSH + c * 8) =
            *((const uint4*)(base + (size_t)i * 1536 + 1024) + c);
    }
    // ---- zero pads: Q/K/V rows 49..63 (4 chunks each) ----
    const uint4 z4 = make_uint4(0u, 0u, 0u, 0u);
    for (int l = tid; l < 15 * 4; l += 128) {
        int r = 49 + (l >> 2), c = l & 3;
        *(uint4*)(Qs + r * QSH + c * 8) = z4;
        *(uint4*)(Ks + r * KSH + c * 8) = z4;
        *(uint4*)(Vs + r * VSH + c * 8) = z4;
    }
    {   // Ps cols 56..71 zero (PV reads cols up to 63)
        int r = tid >> 1, p = tid & 1;
        *(uint4*)(Ps + r * PSH + 56 + p * 8) = z4;
    }
    for (int l = tid; l < 169; l += 128) bs[l] = bias_table[l * HEADS + h];
    __syncthreads();

    const int i0 = wm * 16 + grp;
    const int i1 = i0 + 8;
    const int ri0 = div7(i0), ci0 = i0 - ri0 * 7;
    const int ri1 = div7(i1), ci1 = i1 - ri1 * 7;

    // ldmatrix lane->address components
    const int l7 = lane & 7;
    const int lb = (lane >> 3) & 1;
    const int lt = lane >> 4;
    // A-frag (Q / P): rows (warp m-base + l7 + lb*8), col chunk lt*8
    const uint32_t aQ = smem_u32(Qs) +
        (uint32_t)(((wm * 16 + l7 + lb * 8) * QSH + lt * 8) * 2);
    const uint32_t aP = smem_u32(Ps) +
        (uint32_t)(((wm * 16 + l7 + lb * 8) * PSH + lt * 8) * 2);
    // B-frag non-trans (K): rows (l7 + lt*8), col chunk lb*8
    const uint32_t bK = smem_u32(Ks) +
        (uint32_t)(((l7 + lt * 8) * KSH + lb * 8) * 2);
    // B-frag trans (V row-major): rows (l7 + lb*8), col chunk lt*8
    const uint32_t bV = smem_u32(Vs) +
        (uint32_t)(((l7 + lb * 8) * VSH + lt * 8) * 2);

    // ---- QK^T: k=32 (2 k16-steps), 7 n-tiles ----
    float c[7][4];
    #pragma unroll
    for (int nt = 0; nt < 7; nt++)
        #pragma unroll
        for (int l = 0; l < 4; l++) c[nt][l] = 0.f;

    #pragma unroll
    for (int ks = 0; ks < 2; ks++) {
        const uint32_t kb = (uint32_t)(ks * 32);      // 16 halves
        unsigned a[4];
        ldsm4(a, aQ + kb);
        unsigned bf[8][2];
        #pragma unroll
        for (int np = 0; np < 4; np++) {
            unsigned r[4];
            ldsm4(r, bK + (uint32_t)(np * 16 * KSH * 2) + kb);
            bf[2 * np][0] = r[0]; bf[2 * np][1] = r[1];
            bf[2 * np + 1][0] = r[2]; bf[2 * np + 1][1] = r[3];
        }
        #pragma unroll
        for (int nt = 0; nt < 7; nt++)
            mma_f16(c[nt], a, bf[nt]);
    }

    // ---- softmax numerators -> Ps (half2), row sums via tg-butterfly ----
    float s01 = 0.f, s23 = 0.f;
    #pragma unroll
    for (int nt = 0; nt < 7; nt++) {
        const int j0 = nt * 8 + 2 * tg;
        const int j1 = j0 + 1;
        const int rj0 = div7(j0), cj0 = j0 - rj0 * 7;
        const int rj1 = div7(j1), cj1 = j1 - rj1 * 7;
        float e00 = 0.f, e01 = 0.f, e10 = 0.f, e11 = 0.f;
        if (j0 < WIN) {
            e00 = __expf(c[nt][0] * SCALE + bs[(ri0 - rj0 + 6) * 13 + (ci0 - cj0 + 6)]);
            e10 = __expf(c[nt][2] * SCALE + bs[(ri1 - rj0 + 6) * 13 + (ci1 - cj0 + 6)]);
        }
        if (j1 < WIN) {
            e01 = __expf(c[nt][1] * SCALE + bs[(ri0 - rj1 + 6) * 13 + (ci0 - cj1 + 6)]);
            e11 = __expf(c[nt][3] * SCALE + bs[(ri1 - rj1 + 6) * 13 + (ci1 - cj1 + 6)]);
        }
        s01 += e00 + e01;
        s23 += e10 + e11;
        *(__half2*)(Ps + i0 * PSH + j0) = __floats2half2_rn(e00, e01);
        *(__half2*)(Ps + i1 * PSH + j0) = __floats2half2_rn(e10, e11);
    }
    s01 += __shfl_xor_sync(0xFFFFFFFFu, s01, 1);
    s01 += __shfl_xor_sync(0xFFFFFFFFu, s01, 2);
    s23 += __shfl_xor_sync(0xFFFFFFFFu, s23, 1);
    s23 += __shfl_xor_sync(0xFFFFFFFFu, s23, 2);
    if (tg == 0) {
        inv[i0] = 1.f / s01;
        inv[i1] = 1.f / s23;
    }
    __syncwarp();      // P rows + inv are warp-local

    // ---- PV: k=64 (4 k16-steps), n=32 (2 ldsm4t per step) ----
    float o[4][4];
    #pragma unroll
    for (int nt = 0; nt < 4; nt++)
        #pragma unroll
        for (int l = 0; l < 4; l++) o[nt][l] = 0.f;

    #pragma unroll
    for (int ks = 0; ks < 4; ks++) {
        unsigned a[4];
        ldsm4(a, aP + (uint32_t)(ks * 32));
        unsigned bf[4][2];
        #pragma unroll
        for (int np = 0; np < 2; np++) {
            unsigned r[4];
            // trans: rows = k-rows (ks*16 block), cols = n-group np*16
            ldsm4t(r, bV + (uint32_t)((ks * 16 * VSH + np * 16) * 2));
            bf[2 * np][0] = r[0]; bf[2 * np][1] = r[1];
            bf[2 * np + 1][0] = r[2]; bf[2 * np + 1][1] = r[3];
        }
        #pragma unroll
        for (int nt = 0; nt < 4; nt++)
            mma_f16(o[nt], a, bf[nt]);
    }

    const float v0 = inv[i0];
    const float v1 = inv[i1];
    __half* obase = att + (size_t)bw * WIN * 512 + h * 32;
    #pragma unroll
    for (int nt = 0; nt < 4; nt++) {
        const int d0 = nt * 8 + 2 * tg;
        if (i0 < WIN)
            *(__half2*)(obase + (size_t)i0 * 512 + d0) =
                __floats2half2_rn(o[nt][0] * v0, o[nt][1] * v0);
        if (i1 < WIN)
            *(__half2*)(obase + (size_t)i1 * 512 + d0) =
                __floats2half2_rn(o[nt][2] * v1, o[nt][3] * v1);
    }
}

// --------------------------------- launcher --------------------------------
extern "C" void kernel_launch(void* const* d_in, const int* in_sizes, int n_in,
                              void* d_out, int out_size)
{
    const float* x          = (const float*)d_in[0];
    const float* w_qkv      = (const float*)d_in[1];
    const float* bias_table = (const float*)d_in[2];
    const float* w_out      = (const float*)d_in[3];
    float* out = (float*)d_out;

    __half *qkvh, *atth, *xh, *wqkvT, *woutT;
    cudaGetSymbolAddress((void**)&qkvh,  g_qkvh);
    cudaGetSymbolAddress((void**)&atth,  g_atth);
    cudaGetSymbolAddress((void**)&xh,    g_xh);
    cudaGetSymbolAddress((void**)&wqkvT, g_wqkvT);
    cudaGetSymbolAddress((void**)&woutT, g_woutT);

    cudaFuncSetAttribute(gemm_f16<__half>,
                         cudaFuncAttributeMaxDynamicSharedMemorySize, GSMEM_BYTES);
    cudaFuncSetAttribute(gemm_f16<float>,
                         cudaFuncAttributeMaxDynamicSharedMemorySize, GSMEM_BYTES);

    const long nreal = (long)M_REAL * 512;
    const long ntot  = (long)M_PAD  * 512;
    const long n8real = nreal / 8;
    const long n8tot  = ntot / 8;

    // order keeps the ncu fixed capture slot on gemm K1
    half_pad8<<<(int)((n8tot + 255) / 256), 256>>>(
        (const float4*)x, (uint4*)xh, n8real, n8tot);
    transpose_half<<<dim3(1536 / 32, 512 / 32), dim3(32, 8)>>>(w_qkv, wqkvT, 512, 1536);
    transpose_half<<<dim3(512 / 32, 512 / 32), dim3(32, 8)>>>(w_out, woutT, 512, 512);

    // K1: qkvh = xh @ wqkvT^T
    gemm_f16<__half><<<dim3(1536 / BN, M_PAD / BM), 128, GSMEM_BYTES>>>(
        xh, wqkvT, qkvh, M_REAL, 1536);

    zero_fill_h<<<(64 * 512 / 2 + 255) / 256, 256>>>(atth + nreal, 64 * 512);

    // K2: attention (fp16 tensor-core, ldmatrix fragments)
    attn_f16<<<NWIN * HEADS, 128>>>(qkvh, bias_table, atth);

    // K3: out = atth @ woutT^T
    gemm_f16<float><<<dim3(512 / BN, M_PAD / BM), 128, GSMEM_BYTES>>>(
        atth, woutT, out, M_REAL, 512);
}

// round 16
// speedup vs baseline: 1.3954x; 1.0925x over previous
#include <cuda_runtime.h>
#include <cuda_fp16.h>
#include <cstdint>

// ---------------------------------------------------------------------------
// MultiAxisAttention (Swin window attention) — fp16 HMMA everywhere.
// R16: GEMM BK 32->64 (8 stages, half the barriers), NSTG=2, 3 CTAs/SM
//      preserved (72KB/CTA). Attention/prep = R15 verbatim.
// ---------------------------------------------------------------------------

#define M_REAL 153664            // 16*196*49
#define M_PAD  153728            // 1201*128
#define NWIN   3136
#define HEADS  16
#define WIN    49
#define KDIM   512

__device__ __half g_qkvh[236027904];   // M_REAL*1536
__device__ __half g_atth[78708736];    // M_PAD*512 (pad rows zeroed)
__device__ __half g_xh  [78708736];    // M_PAD*512 (pad rows zeroed)
__device__ __half g_wqkvT[786432];     // [1536][512]
__device__ __half g_woutT[262144];     // [512][512]

// ------------------------------ helpers -----------------------------------
__device__ __forceinline__ uint32_t smem_u32(const void* p) {
    uint32_t a;
    asm("{ .reg .u64 t; cvta.to.shared.u64 t, %1; cvt.u32.u64 %0, t; }"
        : "=r"(a) : "l"(p));
    return a;
}
__device__ __forceinline__ void cp16(uint32_t dst, const void* src) {
    asm volatile("cp.async.cg.shared.global [%0], [%1], 16;\n"
                 :: "r"(dst), "l"(src));
}
#define CP_COMMIT() asm volatile("cp.async.commit_group;\n" ::: "memory")
#define CP_WAIT(n)  asm volatile("cp.async.wait_group %0;\n" :: "n"(n) : "memory")

__device__ __forceinline__ void ldsm4(unsigned* r, uint32_t a) {
    asm volatile("ldmatrix.sync.aligned.m8n8.x4.shared.b16 {%0,%1,%2,%3}, [%4];"
                 : "=r"(r[0]), "=r"(r[1]), "=r"(r[2]), "=r"(r[3]) : "r"(a));
}
__device__ __forceinline__ void ldsm4t(unsigned* r, uint32_t a) {
    asm volatile("ldmatrix.sync.aligned.m8n8.x4.trans.shared.b16 {%0,%1,%2,%3}, [%4];"
                 : "=r"(r[0]), "=r"(r[1]), "=r"(r[2]), "=r"(r[3]) : "r"(a));
}
__device__ __forceinline__ void mma_f16(float* d, const unsigned* a, const unsigned* b) {
    asm volatile(
        "mma.sync.aligned.m16n8k16.row.col.f32.f16.f16.f32 "
        "{%0,%1,%2,%3}, {%4,%5,%6,%7}, {%8,%9}, {%0,%1,%2,%3};\n"
        : "+f"(d[0]), "+f"(d[1]), "+f"(d[2]), "+f"(d[3])
        : "r"(a[0]), "r"(a[1]), "r"(a[2]), "r"(a[3]),
          "r"(b[0]), "r"(b[1]));
}

__device__ __forceinline__ void storeC(float* C, size_t idx, float a, float b) {
    *(float2*)(C + idx) = make_float2(a, b);
}
__device__ __forceinline__ void storeC(__half* C, size_t idx, float a, float b) {
    *(__half2*)(C + idx) = __floats2half2_rn(a, b);
}

// ----------------------------- GEMM (fp16) ---------------------------------
// CTA 128x128, BK=64, 128 threads = 4 warps (2x2), warp tile 64x64.
// 2-stage ring: wait(0) -> sync -> prefetch(t+1) -> compute(t). 8 stages.
// A [M][512] half row-major; B = WT [N][512] half row-major.
#define BM 128
#define BN 128
#define BK 64
#define RSH 72                          // halves per smem row (64+8)
#define OP_HALVES (128 * RSH)           // 9216 per operand per stage
#define STG_HALVES (2 * OP_HALVES)
#define STG_BYTES (STG_HALVES * 2)      // 36864
#define NSTG 2
#define GSMEM_BYTES (NSTG * STG_BYTES)  // 73728

template <typename OutT>
__global__ void __launch_bounds__(128, 3)
gemm_f16(const __half* __restrict__ A, const __half* __restrict__ B,
         OutT* __restrict__ C, int Mreal, int N)
{
    extern __shared__ __half sm[];

    const int tid  = threadIdx.x;
    const int lane = tid & 31;
    const int warp = tid >> 5;          // 0..3
    const int wm   = warp >> 1;
    const int wn   = warp & 1;
    const int grp  = lane >> 2;
    const int tg   = lane & 3;

    const int m0 = blockIdx.y * BM;
    const int n0 = blockIdx.x * BN;
    const uint32_t smb = smem_u32(sm);

    // fill: warp covers 4 rows x 128B; lane -> row=lane>>3, chunk=lane&7
    // STS classes (row+chunk)%8 each 4x per warp -> conflict-free.
    const int frow = warp * 4 + (lane >> 3);    // 0..15, reps +16p (p<8)
    const int fc   = (lane & 7) << 3;           // halves: 0,8,..,56
    const __half*  ag0 = A + (size_t)(m0 + frow) * KDIM + fc;
    const __half*  bg0 = B + (size_t)(n0 + frow) * KDIM + fc;
    const uint32_t ad0 = smb + (uint32_t)((frow * RSH + fc) * 2);
    const uint32_t bd0 = ad0 + OP_HALVES * 2;

    // ldmatrix lane->address components (rows at RSH stride: 16B-group = 16r mod 128)
    const int l7 = lane & 7;
    const int lb = (lane >> 3) & 1;
    const int lt = lane >> 4;
    const uint32_t aL = smb +
        (uint32_t)(((wm * 64 + l7 + lb * 8) * RSH + lt * 8) * 2);
    const uint32_t bL = smb + (uint32_t)(OP_HALVES * 2) +
        (uint32_t)(((wn * 64 + l7 + lt * 8) * RSH + lb * 8) * 2);

    float acc[4][8][4];
    #pragma unroll
    for (int i = 0; i < 4; i++)
        #pragma unroll
        for (int j = 0; j < 8; j++)
            #pragma unroll
            for (int l = 0; l < 4; l++) acc[i][j][l] = 0.f;

    const int T = KDIM / BK;   // 8

    // prologue: stage 0 -> buffer 0
    #pragma unroll
    for (int p = 0; p < 8; p++) {
        cp16(ad0 + (uint32_t)(p * 16 * RSH) * 2, ag0 + (size_t)p * 16 * KDIM);
        cp16(bd0 + (uint32_t)(p * 16 * RSH) * 2, bg0 + (size_t)p * 16 * KDIM);
    }
    CP_COMMIT();

    for (int t = 0; t < T; ++t) {
        CP_WAIT(0);                 // stage t landed (only group outstanding)
        __syncthreads();            // visible to all; prior compute done

        // prefetch stage t+1 into the other buffer (post-sync -> safe)
        if (t + 1 < T) {
            const uint32_t off = (uint32_t)(((t + 1) & 1) * STG_BYTES);
            const __half* ag = ag0 + (t + 1) * BK;
            const __half* bg = bg0 + (t + 1) * BK;
            #pragma unroll
            for (int p = 0; p < 8; p++) {
                cp16(ad0 + off + (uint32_t)(p * 16 * RSH) * 2, ag + (size_t)p * 16 * KDIM);
                cp16(bd0 + off + (uint32_t)(p * 16 * RSH) * 2, bg + (size_t)p * 16 * KDIM);
            }
            CP_COMMIT();
        }

        const uint32_t bufo = (uint32_t)((t & 1) * STG_BYTES);
        const uint32_t aB = aL + bufo;
        const uint32_t bB = bL + bufo;
        #pragma unroll
        for (int ks = 0; ks < 4; ks++) {
            const uint32_t kkb = (uint32_t)(ks * 32);     // 16 halves per step
            unsigned af[4][4], bf[8][2];
            #pragma unroll
            for (int mt = 0; mt < 4; mt++)
                ldsm4(af[mt], aB + (uint32_t)(mt * 16 * RSH * 2) + kkb);
            #pragma unroll
            for (int np = 0; np < 4; np++) {
                unsigned r[4];
                ldsm4(r, bB + (uint32_t)(np * 16 * RSH * 2) + kkb);
                bf[2 * np][0] = r[0]; bf[2 * np][1] = r[1];
                bf[2 * np + 1][0] = r[2]; bf[2 * np + 1][1] = r[3];
            }
            #pragma unroll
            for (int mt = 0; mt < 4; mt++)
                #pragma unroll
                for (int nt = 0; nt < 8; nt++)
                    mma_f16(acc[mt][nt], af[mt], bf[nt]);
        }
    }

    #pragma unroll
    for (int mt = 0; mt < 4; mt++) {
        #pragma unroll
        for (int nt = 0; nt < 8; nt++) {
            int r0 = m0 + wm * 64 + mt * 16 + grp;
            int c  = n0 + wn * 64 + nt * 8 + tg * 2;
            if (r0 < Mreal)
                storeC(C, (size_t)r0 * N + c, acc[mt][nt][0], acc[mt][nt][1]);
            if (r0 + 8 < Mreal)
                storeC(C, (size_t)(r0 + 8) * N + c, acc[mt][nt][2], acc[mt][nt][3]);
        }
    }
}

// ------------------------------ prep kernels -------------------------------
__global__ void half_pad8(const float4* __restrict__ x, uint4* __restrict__ xh,
                          long n8real, long n8tot)
{
    long i = (long)blockIdx.x * blockDim.x + threadIdx.x;
    if (i >= n8tot) return;
    uint4 o = make_uint4(0u, 0u, 0u, 0u);
    if (i < n8real) {
        float4 a = x[2 * i];
        float4 b = x[2 * i + 1];
        __half2 h0 = __floats2half2_rn(a.x, a.y);
        __half2 h1 = __floats2half2_rn(a.z, a.w);
        __half2 h2 = __floats2half2_rn(b.x, b.y);
        __half2 h3 = __floats2half2_rn(b.z, b.w);
        o.x = *(unsigned*)&h0; o.y = *(unsigned*)&h1;
        o.z = *(unsigned*)&h2; o.w = *(unsigned*)&h3;
    }
    xh[i] = o;
}

__global__ void transpose_half(const float* __restrict__ W, __half* __restrict__ WT,
                               int R, int Ccols)
{
    __shared__ float t[32][33];
    const int tx = threadIdx.x, ty = threadIdx.y;
    const int x = blockIdx.x * 32 + tx;
    #pragma unroll
    for (int j = 0; j < 4; j++) {
        int y = blockIdx.y * 32 + ty + j * 8;
        t[ty + j * 8][tx] = W[(size_t)y * Ccols + x];
    }
    __syncthreads();
    const int ox = blockIdx.y * 32 + tx;
    #pragma unroll
    for (int j = 0; j < 4; j++) {
        int oy = blockIdx.x * 32 + ty + j * 8;
        WT[(size_t)oy * R + ox] = __float2half(t[tx][ty + j * 8]);
    }
}

__global__ void zero_fill_h(__half* __restrict__ p, int n)
{
    int i = blockIdx.x * blockDim.x + threadIdx.x;
    if (i < n / 2) ((uint32_t*)p)[i] = 0u;
}

// ----------------------------- attention (fp16 HMMA, ldmatrix) -------------
#define QSH 40    // Qs [64][40]h
#define KSH 40    // Ks [64][40]h (rows 49..63 zero)
#define VSH 40    // Vs [64][40]h (rows 49..63 zero)
#define PSH 72    // Ps [64][72]h (cols j 0..63 used)

__device__ __forceinline__ int div7(int v) { return (v * 37) >> 8; }  // exact 0..55

__global__ void __launch_bounds__(128)
attn_f16(const __half* __restrict__ qkv,
         const float* __restrict__ bias_table,
         __half* __restrict__ att)
{
    __shared__ __half Qs[64 * QSH];
    __shared__ __half Ks[64 * KSH];
    __shared__ __half Vs[64 * VSH];
    __shared__ __half Ps[64 * PSH];
    __shared__ float bs[176];
    __shared__ float inv[64];

    const int h  = blockIdx.x & 15;
    const int bw = blockIdx.x >> 4;
    const int tid  = threadIdx.x;
    const int lane = tid & 31;
    const int wm   = tid >> 5;
    const int grp  = lane >> 2;
    const int tg   = lane & 3;

    const __half* base = qkv + (size_t)bw * WIN * 1536 + h * 32;
    const float SCALE = 0.17677669529663687f;

    for (int l = tid; l < WIN * 4; l += 128) {
        int i = l >> 2, c = l & 3;
        const uint4* row = (const uint4*)(base + (size_t)i * 1536);
        *(uint4*)(Qs + i * QSH + c * 8) = row[c];
        *(uint4*)(Ks + i * KSH + c * 8) =
            *((const uint4*)(base + (size_t)i * 1536 + 512) + c);
        *(uint4*)(Vs + i * VSH + c * 8) =
            *((const uint4*)(base + (size_t)i * 1536 + 1024) + c);
    }
    const uint4 z4 = make_uint4(0u, 0u, 0u, 0u);
    for (int l = tid; l < 15 * 4; l += 128) {
        int r = 49 + (l >> 2), c = l & 3;
        *(uint4*)(Qs + r * QSH + c * 8) = z4;
        *(uint4*)(Ks + r * KSH + c * 8) = z4;
        *(uint4*)(Vs + r * VSH + c * 8) = z4;
    }
    {
        int r = tid >> 1, p = tid & 1;
        *(uint4*)(Ps + r * PSH + 56 + p * 8) = z4;
    }
    for (int l = tid; l < 169; l += 128) bs[l] = bias_table[l * HEADS + h];
    __syncthreads();

    const int i0 = wm * 16 + grp;
    const int i1 = i0 + 8;
    const int ri0 = div7(i0), ci0 = i0 - ri0 * 7;
    const int ri1 = div7(i1), ci1 = i1 - ri1 * 7;

    const int l7 = lane & 7;
    const int lb = (lane >> 3) & 1;
    const int lt = lane >> 4;
    const uint32_t aQ = smem_u32(Qs) +
        (uint32_t)(((wm * 16 + l7 + lb * 8) * QSH + lt * 8) * 2);
    const uint32_t aP = smem_u32(Ps) +
        (uint32_t)(((wm * 16 + l7 + lb * 8) * PSH + lt * 8) * 2);
    const uint32_t bK = smem_u32(Ks) +
        (uint32_t)(((l7 + lt * 8) * KSH + lb * 8) * 2);
    const uint32_t bV = smem_u32(Vs) +
        (uint32_t)(((l7 + lb * 8) * VSH + lt * 8) * 2);

    float c[7][4];
    #pragma unroll
    for (int nt = 0; nt < 7; nt++)
        #pragma unroll
        for (int l = 0; l < 4; l++) c[nt][l] = 0.f;

    #pragma unroll
    for (int ks = 0; ks < 2; ks++) {
        const uint32_t kb = (uint32_t)(ks * 32);
        unsigned a[4];
        ldsm4(a, aQ + kb);
        unsigned bf[8][2];
        #pragma unroll
        for (int np = 0; np < 4; np++) {
            unsigned r[4];
            ldsm4(r, bK + (uint32_t)(np * 16 * KSH * 2) + kb);
            bf[2 * np][0] = r[0]; bf[2 * np][1] = r[1];
            bf[2 * np + 1][0] = r[2]; bf[2 * np + 1][1] = r[3];
        }
        #pragma unroll
        for (int nt = 0; nt < 7; nt++)
            mma_f16(c[nt], a, bf[nt]);
    }

    float s01 = 0.f, s23 = 0.f;
    #pragma unroll
    for (int nt = 0; nt < 7; nt++) {
        const int j0 = nt * 8 + 2 * tg;
        const int j1 = j0 + 1;
        const int rj0 = div7(j0), cj0 = j0 - rj0 * 7;
        const int rj1 = div7(j1), cj1 = j1 - rj1 * 7;
        float e00 = 0.f, e01 = 0.f, e10 = 0.f, e11 = 0.f;
        if (j0 < WIN) {
            e00 = __expf(c[nt][0] * SCALE + bs[(ri0 - rj0 + 6) * 13 + (ci0 - cj0 + 6)]);
            e10 = __expf(c[nt][2] * SCALE + bs[(ri1 - rj0 + 6) * 13 + (ci1 - cj0 + 6)]);
        }
        if (j1 < WIN) {
            e01 = __expf(c[nt][1] * SCALE + bs[(ri0 - rj1 + 6) * 13 + (ci0 - cj1 + 6)]);
            e11 = __expf(c[nt][3] * SCALE + bs[(ri1 - rj1 + 6) * 13 + (ci1 - cj1 + 6)]);
        }
        s01 += e00 + e01;
        s23 += e10 + e11;
        *(__half2*)(Ps + i0 * PSH + j0) = __floats2half2_rn(e00, e01);
        *(__half2*)(Ps + i1 * PSH + j0) = __floats2half2_rn(e10, e11);
    }
    s01 += __shfl_xor_sync(0xFFFFFFFFu, s01, 1);
    s01 += __shfl_xor_sync(0xFFFFFFFFu, s01, 2);
    s23 += __shfl_xor_sync(0xFFFFFFFFu, s23, 1);
    s23 += __shfl_xor_sync(0xFFFFFFFFu, s23, 2);
    if (tg == 0) {
        inv[i0] = 1.f / s01;
        inv[i1] = 1.f / s23;
    }
    __syncwarp();

    float o[4][4];
    #pragma unroll
    for (int nt = 0; nt < 4; nt++)
        #pragma unroll
        for (int l = 0; l < 4; l++) o[nt][l] = 0.f;

    #pragma unroll
    for (int ks = 0; ks < 4; ks++) {
        unsigned a[4];
        ldsm4(a, aP + (uint32_t)(ks * 32));
        unsigned bf[4][2];
        #pragma unroll
        for (int np = 0; np < 2; np++) {
            unsigned r[4];
            ldsm4t(r, bV + (uint32_t)((ks * 16 * VSH + np * 16) * 2));
            bf[2 * np][0] = r[0]; bf[2 * np][1] = r[1];
            bf[2 * np + 1][0] = r[2]; bf[2 * np + 1][1] = r[3];
        }
        #pragma unroll
        for (int nt = 0; nt < 4; nt++)
            mma_f16(o[nt], a, bf[nt]);
    }

    const float v0 = inv[i0];
    const float v1 = inv[i1];
    __half* obase = att + (size_t)bw * WIN * 512 + h * 32;
    #pragma unroll
    for (int nt = 0; nt < 4; nt++) {
        const int d0 = nt * 8 + 2 * tg;
        if (i0 < WIN)
            *(__half2*)(obase + (size_t)i0 * 512 + d0) =
                __floats2half2_rn(o[nt][0] * v0, o[nt][1] * v0);
        if (i1 < WIN)
            *(__half2*)(obase + (size_t)i1 * 512 + d0) =
                __floats2half2_rn(o[nt][2] * v1, o[nt][3] * v1);
    }
}

// --------------------------------- launcher --------------------------------
extern "C" void kernel_launch(void* const* d_in, const int* in_sizes, int n_in,
                              void* d_out, int out_size)
{
    const float* x          = (const float*)d_in[0];
    const float* w_qkv      = (const float*)d_in[1];
    const float* bias_table = (const float*)d_in[2];
    const float* w_out      = (const float*)d_in[3];
    float* out = (float*)d_out;

    __half *qkvh, *atth, *xh, *wqkvT, *woutT;
    cudaGetSymbolAddress((void**)&qkvh,  g_qkvh);
    cudaGetSymbolAddress((void**)&atth,  g_atth);
    cudaGetSymbolAddress((void**)&xh,    g_xh);
    cudaGetSymbolAddress((void**)&wqkvT, g_wqkvT);
    cudaGetSymbolAddress((void**)&woutT, g_woutT);

    cudaFuncSetAttribute(gemm_f16<__half>,
                         cudaFuncAttributeMaxDynamicSharedMemorySize, GSMEM_BYTES);
    cudaFuncSetAttribute(gemm_f16<float>,
                         cudaFuncAttributeMaxDynamicSharedMemorySize, GSMEM_BYTES);

    const long nreal = (long)M_REAL * 512;
    const long ntot  = (long)M_PAD  * 512;
    const long n8real = nreal / 8;
    const long n8tot  = ntot / 8;

    // order keeps the ncu fixed capture slot on gemm K1
    half_pad8<<<(int)((n8tot + 255) / 256), 256>>>(
        (const float4*)x, (uint4*)xh, n8real, n8tot);
    transpose_half<<<dim3(1536 / 32, 512 / 32), dim3(32, 8)>>>(w_qkv, wqkvT, 512, 1536);
    transpose_half<<<dim3(512 / 32, 512 / 32), dim3(32, 8)>>>(w_out, woutT, 512, 512);

    // K1: qkvh = xh @ wqkvT^T
    gemm_f16<__half><<<dim3(1536 / BN, M_PAD / BM), 128, GSMEM_BYTES>>>(
        xh, wqkvT, qkvh, M_REAL, 1536);

    zero_fill_h<<<(64 * 512 / 2 + 255) / 256, 256>>>(atth + nreal, 64 * 512);

    // K2: attention
    attn_f16<<<NWIN * HEADS, 128>>>(qkvh, bias_table, atth);

    // K3: out = atth @ woutT^T
    gemm_f16<float><<<dim3(512 / BN, M_PAD / BM), 128, GSMEM_BYTES>>>(
        atth, woutT, out, M_REAL, 512);
}

// round 17
// speedup vs baseline: 1.4450x; 1.0356x over previous
#include <cuda_runtime.h>
#include <cuda_fp16.h>
#include <cstdint>

// ---------------------------------------------------------------------------
// MultiAxisAttention (Swin window attention) — fp16 HMMA everywhere.
// R17: GEMM = R16 (BK=64, 2-stage, 3 CTAs/SM) with ks=0 peeled ahead of the
//      prefetch (kills post-barrier issue bubble). Dead pad-zeroing removed
//      (pad rows provably never reach stored output). Attention = R15/16.
// ---------------------------------------------------------------------------

#define M_REAL 153664            // 16*196*49
#define M_PAD  153728            // 1201*128
#define NWIN   3136
#define HEADS  16
#define WIN    49
#define KDIM   512

__device__ __half g_qkvh[236027904];   // M_REAL*1536
__device__ __half g_atth[78708736];    // M_PAD*512
__device__ __half g_xh  [78708736];    // M_PAD*512
__device__ __half g_wqkvT[786432];     // [1536][512]
__device__ __half g_woutT[262144];     // [512][512]

// ------------------------------ helpers -----------------------------------
__device__ __forceinline__ uint32_t smem_u32(const void* p) {
    uint32_t a;
    asm("{ .reg .u64 t; cvta.to.shared.u64 t, %1; cvt.u32.u64 %0, t; }"
        : "=r"(a) : "l"(p));
    return a;
}
__device__ __forceinline__ void cp16(uint32_t dst, const void* src) {
    asm volatile("cp.async.cg.shared.global [%0], [%1], 16;\n"
                 :: "r"(dst), "l"(src));
}
#define CP_COMMIT() asm volatile("cp.async.commit_group;\n" ::: "memory")
#define CP_WAIT(n)  asm volatile("cp.async.wait_group %0;\n" :: "n"(n) : "memory")

__device__ __forceinline__ void ldsm4(unsigned* r, uint32_t a) {
    asm volatile("ldmatrix.sync.aligned.m8n8.x4.shared.b16 {%0,%1,%2,%3}, [%4];"
                 : "=r"(r[0]), "=r"(r[1]), "=r"(r[2]), "=r"(r[3]) : "r"(a));
}
__device__ __forceinline__ void ldsm4t(unsigned* r, uint32_t a) {
    asm volatile("ldmatrix.sync.aligned.m8n8.x4.trans.shared.b16 {%0,%1,%2,%3}, [%4];"
                 : "=r"(r[0]), "=r"(r[1]), "=r"(r[2]), "=r"(r[3]) : "r"(a));
}
__device__ __forceinline__ void mma_f16(float* d, const unsigned* a, const unsigned* b) {
    asm volatile(
        "mma.sync.aligned.m16n8k16.row.col.f32.f16.f16.f32 "
        "{%0,%1,%2,%3}, {%4,%5,%6,%7}, {%8,%9}, {%0,%1,%2,%3};\n"
        : "+f"(d[0]), "+f"(d[1]), "+f"(d[2]), "+f"(d[3])
        : "r"(a[0]), "r"(a[1]), "r"(a[2]), "r"(a[3]),
          "r"(b[0]), "r"(b[1]));
}

__device__ __forceinline__ void storeC(float* C, size_t idx, float a, float b) {
    *(float2*)(C + idx) = make_float2(a, b);
}
__device__ __forceinline__ void storeC(__half* C, size_t idx, float a, float b) {
    *(__half2*)(C + idx) = __floats2half2_rn(a, b);
}

// ----------------------------- GEMM (fp16) ---------------------------------
// CTA 128x128, BK=64, 128 threads = 4 warps (2x2), warp tile 64x64.
// 2-stage ring; ks=0 peeled ahead of prefetch issue.
#define BM 128
#define BN 128
#define BK 64
#define RSH 72                          // halves per smem row (64+8)
#define OP_HALVES (128 * RSH)           // 9216 per operand per stage
#define STG_HALVES (2 * OP_HALVES)
#define STG_BYTES (STG_HALVES * 2)      // 36864
#define NSTG 2
#define GSMEM_BYTES (NSTG * STG_BYTES)  // 73728

template <typename OutT>
__global__ void __launch_bounds__(128, 3)
gemm_f16(const __half* __restrict__ A, const __half* __restrict__ B,
         OutT* __restrict__ C, int Mreal, int N)
{
    extern __shared__ __half sm[];

    const int tid  = threadIdx.x;
    const int lane = tid & 31;
    const int warp = tid >> 5;          // 0..3
    const int wm   = warp >> 1;
    const int wn   = warp & 1;
    const int grp  = lane >> 2;
    const int tg   = lane & 3;

    const int m0 = blockIdx.y * BM;
    const int n0 = blockIdx.x * BN;
    const uint32_t smb = smem_u32(sm);

    // fill: warp covers 4 rows x 128B; lane -> row=lane>>3, chunk=lane&7
    const int frow = warp * 4 + (lane >> 3);    // 0..15, reps +16p (p<8)
    const int fc   = (lane & 7) << 3;           // halves: 0,8,..,56
    const __half*  ag0 = A + (size_t)(m0 + frow) * KDIM + fc;
    const __half*  bg0 = B + (size_t)(n0 + frow) * KDIM + fc;
    const uint32_t ad0 = smb + (uint32_t)((frow * RSH + fc) * 2);
    const uint32_t bd0 = ad0 + OP_HALVES * 2;

    const int l7 = lane & 7;
    const int lb = (lane >> 3) & 1;
    const int lt = lane >> 4;
    const uint32_t aL = smb +
        (uint32_t)(((wm * 64 + l7 + lb * 8) * RSH + lt * 8) * 2);
    const uint32_t bL = smb + (uint32_t)(OP_HALVES * 2) +
        (uint32_t)(((wn * 64 + l7 + lt * 8) * RSH + lb * 8) * 2);

    float acc[4][8][4];
    #pragma unroll
    for (int i = 0; i < 4; i++)
        #pragma unroll
        for (int j = 0; j < 8; j++)
            #pragma unroll
            for (int l = 0; l < 4; l++) acc[i][j][l] = 0.f;

    const int T = KDIM / BK;   // 8

    // prologue: stage 0 -> buffer 0
    #pragma unroll
    for (int p = 0; p < 8; p++) {
        cp16(ad0 + (uint32_t)(p * 16 * RSH) * 2, ag0 + (size_t)p * 16 * KDIM);
        cp16(bd0 + (uint32_t)(p * 16 * RSH) * 2, bg0 + (size_t)p * 16 * KDIM);
    }
    CP_COMMIT();

    for (int t = 0; t < T; ++t) {
        CP_WAIT(0);
        __syncthreads();

        const uint32_t bufo = (uint32_t)((t & 1) * STG_BYTES);
        const uint32_t aB = aL + bufo;
        const uint32_t bB = bL + bufo;

        // ---- ks = 0 first: start MMAs immediately after the barrier ----
        {
            unsigned af[4][4], bf[8][2];
            #pragma unroll
            for (int mt = 0; mt < 4; mt++)
                ldsm4(af[mt], aB + (uint32_t)(mt * 16 * RSH * 2));
            #pragma unroll
            for (int np = 0; np < 4; np++) {
                unsigned r[4];
                ldsm4(r, bB + (uint32_t)(np * 16 * RSH * 2));
                bf[2 * np][0] = r[0]; bf[2 * np][1] = r[1];
                bf[2 * np + 1][0] = r[2]; bf[2 * np + 1][1] = r[3];
            }
            #pragma unroll
            for (int mt = 0; mt < 4; mt++)
                #pragma unroll
                for (int nt = 0; nt < 8; nt++)
                    mma_f16(acc[mt][nt], af[mt], bf[nt]);
        }

        // ---- prefetch stage t+1 (lands while ks=1..3 compute) ----
        if (t + 1 < T) {
            const uint32_t off = (uint32_t)(((t + 1) & 1) * STG_BYTES);
            const __half* ag = ag0 + (t + 1) * BK;
            const __half* bg = bg0 + (t + 1) * BK;
            #pragma unroll
            for (int p = 0; p < 8; p++) {
                cp16(ad0 + off + (uint32_t)(p * 16 * RSH) * 2, ag + (size_t)p * 16 * KDIM);
                cp16(bd0 + off + (uint32_t)(p * 16 * RSH) * 2, bg + (size_t)p * 16 * KDIM);
            }
            CP_COMMIT();
        }

        // ---- ks = 1..3 ----
        #pragma unroll
        for (int ks = 1; ks < 4; ks++) {
            const uint32_t kkb = (uint32_t)(ks * 32);
            unsigned af[4][4], bf[8][2];
            #pragma unroll
            for (int mt = 0; mt < 4; mt++)
                ldsm4(af[mt], aB + (uint32_t)(mt * 16 * RSH * 2) + kkb);
            #pragma unroll
            for (int np = 0; np < 4; np++) {
                unsigned r[4];
                ldsm4(r, bB + (uint32_t)(np * 16 * RSH * 2) + kkb);
                bf[2 * np][0] = r[0]; bf[2 * np][1] = r[1];
                bf[2 * np + 1][0] = r[2]; bf[2 * np + 1][1] = r[3];
            }
            #pragma unroll
            for (int mt = 0; mt < 4; mt++)
                #pragma unroll
                for (int nt = 0; nt < 8; nt++)
                    mma_f16(acc[mt][nt], af[mt], bf[nt]);
        }
    }

    #pragma unroll
    for (int mt = 0; mt < 4; mt++) {
        #pragma unroll
        for (int nt = 0; nt < 8; nt++) {
            int r0 = m0 + wm * 64 + mt * 16 + grp;
            int c  = n0 + wn * 64 + nt * 8 + tg * 2;
            if (r0 < Mreal)
                storeC(C, (size_t)r0 * N + c, acc[mt][nt][0], acc[mt][nt][1]);
            if (r0 + 8 < Mreal)
                storeC(C, (size_t)(r0 + 8) * N + c, acc[mt][nt][2], acc[mt][nt][3]);
        }
    }
}

// ------------------------------ prep kernels -------------------------------
// real rows only: A pad rows feed only guarded (never-stored) output rows.
__global__ void half_conv8(const float4* __restrict__ x, uint4* __restrict__ xh,
                           long n8real)
{
    long i = (long)blockIdx.x * blockDim.x + threadIdx.x;
    if (i >= n8real) return;
    float4 a = x[2 * i];
    float4 b = x[2 * i + 1];
    __half2 h0 = __floats2half2_rn(a.x, a.y);
    __half2 h1 = __floats2half2_rn(a.z, a.w);
    __half2 h2 = __floats2half2_rn(b.x, b.y);
    __half2 h3 = __floats2half2_rn(b.z, b.w);
    uint4 o;
    o.x = *(unsigned*)&h0; o.y = *(unsigned*)&h1;
    o.z = *(unsigned*)&h2; o.w = *(unsigned*)&h3;
    xh[i] = o;
}

__global__ void transpose_half(const float* __restrict__ W, __half* __restrict__ WT,
                               int R, int Ccols)
{
    __shared__ float t[32][33];
    const int tx = threadIdx.x, ty = threadIdx.y;
    const int x = blockIdx.x * 32 + tx;
    #pragma unroll
    for (int j = 0; j < 4; j++) {
        int y = blockIdx.y * 32 + ty + j * 8;
        t[ty + j * 8][tx] = W[(size_t)y * Ccols + x];
    }
    __syncthreads();
    const int ox = blockIdx.y * 32 + tx;
    #pragma unroll
    for (int j = 0; j < 4; j++) {
        int oy = blockIdx.x * 32 + ty + j * 8;
        WT[(size_t)oy * R + ox] = __float2half(t[tx][ty + j * 8]);
    }
}

// ----------------------------- attention (fp16 HMMA, ldmatrix) -------------
#define QSH 40
#define KSH 40
#define VSH 40
#define PSH 72

__device__ __forceinline__ int div7(int v) { return (v * 37) >> 8; }  // exact 0..55

__global__ void __launch_bounds__(128)
attn_f16(const __half* __restrict__ qkv,
         const float* __restrict__ bias_table,
         __half* __restrict__ att)
{
    __shared__ __half Qs[64 * QSH];
    __shared__ __half Ks[64 * KSH];
    __shared__ __half Vs[64 * VSH];
    __shared__ __half Ps[64 * PSH];
    __shared__ float bs[176];
    __shared__ float inv[64];

    const int h  = blockIdx.x & 15;
    const int bw = blockIdx.x >> 4;
    const int tid  = threadIdx.x;
    const int lane = tid & 31;
    const int wm   = tid >> 5;
    const int grp  = lane >> 2;
    const int tg   = lane & 3;

    const __half* base = qkv + (size_t)bw * WIN * 1536 + h * 32;
    const float SCALE = 0.17677669529663687f;

    for (int l = tid; l < WIN * 4; l += 128) {
        int i = l >> 2, c = l & 3;
        const uint4* row = (const uint4*)(base + (size_t)i * 1536);
        *(uint4*)(Qs + i * QSH + c * 8) = row[c];
        *(uint4*)(Ks + i * KSH + c * 8) =
            *((const uint4*)(base + (size_t)i * 1536 + 512) + c);
        *(uint4*)(Vs + i * VSH + c * 8) =
            *((const uint4*)(base + (size_t)i * 1536 + 1024) + c);
    }
    const uint4 z4 = make_uint4(0u, 0u, 0u, 0u);
    for (int l = tid; l < 15 * 4; l += 128) {
        int r = 49 + (l >> 2), c = l & 3;
        *(uint4*)(Qs + r * QSH + c * 8) = z4;
        *(uint4*)(Ks + r * KSH + c * 8) = z4;
        *(uint4*)(Vs + r * VSH + c * 8) = z4;
    }
    {
        int r = tid >> 1, p = tid & 1;
        *(uint4*)(Ps + r * PSH + 56 + p * 8) = z4;
    }
    for (int l = tid; l < 169; l += 128) bs[l] = bias_table[l * HEADS + h];
    __syncthreads();

    const int i0 = wm * 16 + grp;
    const int i1 = i0 + 8;
    const int ri0 = div7(i0), ci0 = i0 - ri0 * 7;
    const int ri1 = div7(i1), ci1 = i1 - ri1 * 7;

    const int l7 = lane & 7;
    const int lb = (lane >> 3) & 1;
    const int lt = lane >> 4;
    const uint32_t aQ = smem_u32(Qs) +
        (uint32_t)(((wm * 16 + l7 + lb * 8) * QSH + lt * 8) * 2);
    const uint32_t aP = smem_u32(Ps) +
        (uint32_t)(((wm * 16 + l7 + lb * 8) * PSH + lt * 8) * 2);
    const uint32_t bK = smem_u32(Ks) +
        (uint32_t)(((l7 + lt * 8) * KSH + lb * 8) * 2);
    const uint32_t bV = smem_u32(Vs) +
        (uint32_t)(((l7 + lb * 8) * VSH + lt * 8) * 2);

    float c[7][4];
    #pragma unroll
    for (int nt = 0; nt < 7; nt++)
        #pragma unroll
        for (int l = 0; l < 4; l++) c[nt][l] = 0.f;

    #pragma unroll
    for (int ks = 0; ks < 2; ks++) {
        const uint32_t kb = (uint32_t)(ks * 32);
        unsigned a[4];
        ldsm4(a, aQ + kb);
        unsigned bf[8][2];
        #pragma unroll
        for (int np = 0; np < 4; np++) {
            unsigned r[4];
            ldsm4(r, bK + (uint32_t)(np * 16 * KSH * 2) + kb);
            bf[2 * np][0] = r[0]; bf[2 * np][1] = r[1];
            bf[2 * np + 1][0] = r[2]; bf[2 * np + 1][1] = r[3];
        }
        #pragma unroll
        for (int nt = 0; nt < 7; nt++)
            mma_f16(c[nt], a, bf[nt]);
    }

    float s01 = 0.f, s23 = 0.f;
    #pragma unroll
    for (int nt = 0; nt < 7; nt++) {
        const int j0 = nt * 8 + 2 * tg;
        const int j1 = j0 + 1;
        const int rj0 = div7(j0), cj0 = j0 - rj0 * 7;
        const int rj1 = div7(j1), cj1 = j1 - rj1 * 7;
        float e00 = 0.f, e01 = 0.f, e10 = 0.f, e11 = 0.f;
        if (j0 < WIN) {
            e00 = __expf(c[nt][0] * SCALE + bs[(ri0 - rj0 + 6) * 13 + (ci0 - cj0 + 6)]);
            e10 = __expf(c[nt][2] * SCALE + bs[(ri1 - rj0 + 6) * 13 + (ci1 - cj0 + 6)]);
        }
        if (j1 < WIN) {
            e01 = __expf(c[nt][1] * SCALE + bs[(ri0 - rj1 + 6) * 13 + (ci0 - cj1 + 6)]);
            e11 = __expf(c[nt][3] * SCALE + bs[(ri1 - rj1 + 6) * 13 + (ci1 - cj1 + 6)]);
        }
        s01 += e00 + e01;
        s23 += e10 + e11;
        *(__half2*)(Ps + i0 * PSH + j0) = __floats2half2_rn(e00, e01);
        *(__half2*)(Ps + i1 * PSH + j0) = __floats2half2_rn(e10, e11);
    }
    s01 += __shfl_xor_sync(0xFFFFFFFFu, s01, 1);
    s01 += __shfl_xor_sync(0xFFFFFFFFu, s01, 2);
    s23 += __shfl_xor_sync(0xFFFFFFFFu, s23, 1);
    s23 += __shfl_xor_sync(0xFFFFFFFFu, s23, 2);
    if (tg == 0) {
        inv[i0] = 1.f / s01;
        inv[i1] = 1.f / s23;
    }
    __syncwarp();

    float o[4][4];
    #pragma unroll
    for (int nt = 0; nt < 4; nt++)
        #pragma unroll
        for (int l = 0; l < 4; l++) o[nt][l] = 0.f;

    #pragma unroll
    for (int ks = 0; ks < 4; ks++) {
        unsigned a[4];
        ldsm4(a, aP + (uint32_t)(ks * 32));
        unsigned bf[4][2];
        #pragma unroll
        for (int np = 0; np < 2; np++) {
            unsigned r[4];
            ldsm4t(r, bV + (uint32_t)((ks * 16 * VSH + np * 16) * 2));
            bf[2 * np][0] = r[0]; bf[2 * np][1] = r[1];
            bf[2 * np + 1][0] = r[2]; bf[2 * np + 1][1] = r[3];
        }
        #pragma unroll
        for (int nt = 0; nt < 4; nt++)
            mma_f16(o[nt], a, bf[nt]);
    }

    const float v0 = inv[i0];
    const float v1 = inv[i1];
    __half* obase = att + (size_t)bw * WIN * 512 + h * 32;
    #pragma unroll
    for (int nt = 0; nt < 4; nt++) {
        const int d0 = nt * 8 + 2 * tg;
        if (i0 < WIN)
            *(__half2*)(obase + (size_t)i0 * 512 + d0) =
                __floats2half2_rn(o[nt][0] * v0, o[nt][1] * v0);
        if (i1 < WIN)
            *(__half2*)(obase + (size_t)i1 * 512 + d0) =
                __floats2half2_rn(o[nt][2] * v1, o[nt][3] * v1);
    }
}

// --------------------------------- launcher --------------------------------
extern "C" void kernel_launch(void* const* d_in, const int* in_sizes, int n_in,
                              void* d_out, int out_size)
{
    const float* x          = (const float*)d_in[0];
    const float* w_qkv      = (const float*)d_in[1];
    const float* bias_table = (const float*)d_in[2];
    const float* w_out      = (const float*)d_in[3];
    float* out = (float*)d_out;

    __half *qkvh, *atth, *xh, *wqkvT, *woutT;
    cudaGetSymbolAddress((void**)&qkvh,  g_qkvh);
    cudaGetSymbolAddress((void**)&atth,  g_atth);
    cudaGetSymbolAddress((void**)&xh,    g_xh);
    cudaGetSymbolAddress((void**)&wqkvT, g_wqkvT);
    cudaGetSymbolAddress((void**)&woutT, g_woutT);

    cudaFuncSetAttribute(gemm_f16<__half>,
                         cudaFuncAttributeMaxDynamicSharedMemorySize, GSMEM_BYTES);
    cudaFuncSetAttribute(gemm_f16<float>,
                         cudaFuncAttributeMaxDynamicSharedMemorySize, GSMEM_BYTES);

    const long nreal = (long)M_REAL * 512;
    const long n8real = nreal / 8;

    // order keeps the ncu fixed capture slot on gemm K1
    half_conv8<<<(int)((n8real + 255) / 256), 256>>>(
        (const float4*)x, (uint4*)xh, n8real);
    transpose_half<<<dim3(1536 / 32, 512 / 32), dim3(32, 8)>>>(w_qkv, wqkvT, 512, 1536);
    transpose_half<<<dim3(512 / 32, 512 / 32), dim3(32, 8)>>>(w_out, woutT, 512, 512);

    // K1: qkvh = xh @ wqkvT^T
    gemm_f16<__half><<<dim3(1536 / BN, M_PAD / BM), 128, GSMEM_BYTES>>>(
        xh, wqkvT, qkvh, M_REAL, 1536);

    // K2: attention
    attn_f16<<<NWIN * HEADS, 128>>>(qkvh, bias_table, atth);

    // K3: out = atth @ woutT^T
    gemm_f16<float><<<dim3(512 / BN, M_PAD / BM), 128, GSMEM_BYTES>>>(
        atth, woutT, out, M_REAL, 512);
}